// round 10
// baseline (speedup 1.0000x reference)
#include <cuda_runtime.h>
#include <cuda_fp16.h>

#define NN 100000
#define NE 1600000
#define CH 64
#define NT 128                 // nodes per qkvs tile
#define NTILES 782             // ceil(NN/NT)
#define WMAT 4416              // floats per matrix in w_s (64*68 + skew pad)
#define XSZ  8512              // x tile floats (64*132 + skew pad)

typedef unsigned long long ull;

// Scratch (device globals — no allocation allowed)
__device__ __align__(16) __half g_qh[NN*CH];   // fp16 q
__device__ __align__(16) __half g_kh[NN*CH];   // fp16 k
__device__ __align__(16) __half g_vh[NN*CH];   // fp16 v
__device__ __align__(16) __half g_agg[NN*CH];  // fp16 accumulator (RED.f16x2)
__device__ __align__(16) float g_skip[NN*CH];
__device__ float g_den[NN];
__device__ double g_red[2];
__device__ int g_idx64;

__device__ __forceinline__ ull ffma2(ull a, ull b, ull c){
    ull d;
    asm("fma.rn.f32x2 %0, %1, %2, %3;" : "=l"(d) : "l"(a), "l"(b), "l"(c));
    return d;
}
__device__ __forceinline__ ull splat2(float f){
    ull r;
    asm("mov.b64 %0, {%1, %1};" : "=l"(r) : "f"(f));
    return r;
}
__device__ __forceinline__ void unpack2(ull a, float& lo, float& hi){
    asm("mov.b64 {%0, %1}, %2;" : "=f"(lo), "=f"(hi) : "l"(a));
}
__device__ __forceinline__ uint2 pack_h4(float4 f){
    __half2 a01 = __floats2half2_rn(f.x, f.y);
    __half2 a23 = __floats2half2_rn(f.z, f.w);
    uint2 u;
    u.x = *reinterpret_cast<unsigned*>(&a01);
    u.y = *reinterpret_cast<unsigned*>(&a23);
    return u;
}

// ---------------------------------------------------------------------------
// zero accumulators + reduction cells
// ---------------------------------------------------------------------------
__global__ void k_zero(){
    int i = blockIdx.x*blockDim.x + threadIdx.x;
    if (i < NN*8)              // agg: NN*CH halves = NN*8 uint4
        reinterpret_cast<uint4*>(g_agg)[i] = make_uint4(0u,0u,0u,0u);
    if (i < NN/4)
        reinterpret_cast<float4*>(g_den)[i] = make_float4(0.f,0.f,0.f,0.f);
    if (i == 0){ g_red[0] = 0.0; g_red[1] = 0.0; }
}

// ---------------------------------------------------------------------------
// detect dtype of edge_index (int64 vs int32), 1 warp
// ---------------------------------------------------------------------------
__global__ void k_detect(const unsigned int* __restrict__ ei32){
    unsigned int hi = ei32[2*threadIdx.x + 1];
    unsigned int b = __ballot_sync(0xffffffffu, hi != 0u);
    if (threadIdx.x == 0) g_idx64 = (b == 0u);
}

// ---------------------------------------------------------------------------
// qkvs: register-tiled GEMM (4ch x 8node x 2mat = 64 fp32 acc / thread),
// skewed smem. Outputs: q,k,v -> fp16 ; skip -> fp32.
// ---------------------------------------------------------------------------
#define QKV_SMEM_BYTES ((4*WMAT + XSZ + 256)*4)

__global__ void __launch_bounds__(256, 2) k_qkvs(
    const float* __restrict__ geo, const float* __restrict__ euc,
    const float* __restrict__ Wq, const float* __restrict__ Wk,
    const float* __restrict__ Wv, const float* __restrict__ Wsk,
    const float* __restrict__ bq, const float* __restrict__ bk,
    const float* __restrict__ bv, const float* __restrict__ bsk)
{
    extern __shared__ float sm[];
    float* w_s = sm;                       // [4][WMAT]  w[m][kk][c] skewed
    float* x_s = sm + 4*WMAT;              // [XSZ]      x[kk][nl]   skewed
    float* b_s = x_s + XSZ;                // [4][64]

    const int tid = threadIdx.x;

    // stage W transposed+skewed (one-time)
    {
        const float4* Wsrc[4] = {(const float4*)Wq, (const float4*)Wk,
                                 (const float4*)Wv, (const float4*)Wsk};
        #pragma unroll
        for (int j = 0; j < 16; j++){
            int f = j*256 + tid;           // 0..4095
            int m = f >> 10, r = f & 1023;
            int c = r >> 4, kc = r & 15;
            float4 v = Wsrc[m][c*16 + kc];
            float* wb = w_s + m*WMAT + 276*kc + c;
            wb[0]   = v.x;
            wb[68]  = v.y;
            wb[136] = v.z;
            wb[204] = v.w;
        }
        if (tid < 64){
            b_s[tid]       = bq[tid];
            b_s[64 + tid]  = bk[tid];
            b_s[128 + tid] = bv[tid];
            b_s[192 + tid] = bsk[tid];
        }
    }

    const int cg = tid >> 4;               // 0..15 -> c0 = 4*cg
    const int ng = tid & 15;               // 0..15 -> n0 = 8*ng
    const int c0 = cg*4;

    #pragma unroll 1
    for (int t = blockIdx.x; t < NTILES; t += gridDim.x){
        const int base = t*NT;
        #pragma unroll 1
        for (int ph = 0; ph < 2; ph++){
            const float* X = ph ? geo : euc;
            const int mA = ph ? 1 : 0;      // k : q   (fp16 out)
            const int mB = ph ? 2 : 3;      // v : skip
            __half* OA   = ph ? g_kh : g_qh;

            __syncthreads();                // x_s free from previous readers
            #pragma unroll
            for (int j = 0; j < 8; j++){
                int f = j*256 + tid;        // 0..2047
                int nl = f >> 4;            // 0..127
                int kc = f & 15;
                int node = min(base + nl, NN-1);
                float4 v = *reinterpret_cast<const float4*>(
                    X + (size_t)node*CH + kc*4);
                float* xb = x_s + 532*kc + nl;
                xb[0]   = v.x;
                xb[132] = v.y;
                xb[264] = v.z;
                xb[396] = v.w;
            }
            __syncthreads();

            ull acc[2][4][4];
            #pragma unroll
            for (int a = 0; a < 2; a++)
                #pragma unroll
                for (int b = 0; b < 4; b++)
                    #pragma unroll
                    for (int c = 0; c < 4; c++) acc[a][b][c] = 0ull;

            const float* wArow = w_s + mA*WMAT + c0;
            const float* wBrow = w_s + mB*WMAT + c0;
            const float* xrow  = x_s + ng*8;

            #pragma unroll 8
            for (int kk = 0; kk < 64; kk++){
                const int xo = kk*132 + (kk>>2)*4;
                const int wo = kk*68  + (kk>>2)*4;
                ulonglong2 xa = *reinterpret_cast<const ulonglong2*>(xrow + xo);
                ulonglong2 xb = *reinterpret_cast<const ulonglong2*>(xrow + xo + 4);
                float4 wA = *reinterpret_cast<const float4*>(wArow + wo);
                float4 wB = *reinterpret_cast<const float4*>(wBrow + wo);
                #pragma unroll
                for (int ci = 0; ci < 4; ci++){
                    ull sA = splat2((&wA.x)[ci]);
                    acc[0][ci][0] = ffma2(xa.x, sA, acc[0][ci][0]);
                    acc[0][ci][1] = ffma2(xa.y, sA, acc[0][ci][1]);
                    acc[0][ci][2] = ffma2(xb.x, sA, acc[0][ci][2]);
                    acc[0][ci][3] = ffma2(xb.y, sA, acc[0][ci][3]);
                }
                #pragma unroll
                for (int ci = 0; ci < 4; ci++){
                    ull sB = splat2((&wB.x)[ci]);
                    acc[1][ci][0] = ffma2(xa.x, sB, acc[1][ci][0]);
                    acc[1][ci][1] = ffma2(xa.y, sB, acc[1][ci][1]);
                    acc[1][ci][2] = ffma2(xb.x, sB, acc[1][ci][2]);
                    acc[1][ci][3] = ffma2(xb.y, sB, acc[1][ci][3]);
                }
            }

            // epilogue: bias; A -> fp16; B -> fp16 (v) or fp32 (skip)
            float biasA[4], biasB[4];
            #pragma unroll
            for (int ci = 0; ci < 4; ci++){
                biasA[ci] = b_s[mA*64 + c0 + ci];
                biasB[ci] = b_s[mB*64 + c0 + ci];
            }
            const int n0 = base + ng*8;
            #pragma unroll
            for (int np = 0; np < 4; np++){
                float4 loA, hiA, loB, hiB;
                #pragma unroll
                for (int ci = 0; ci < 4; ci++){
                    float lo, hi;
                    unpack2(acc[0][ci][np], lo, hi);
                    (&loA.x)[ci] = lo + biasA[ci];
                    (&hiA.x)[ci] = hi + biasA[ci];
                    unpack2(acc[1][ci][np], lo, hi);
                    (&loB.x)[ci] = lo + biasB[ci];
                    (&hiB.x)[ci] = hi + biasB[ci];
                }
                const int nlo = n0 + 2*np, nhi = n0 + 2*np + 1;
                if (nlo < NN){
                    *reinterpret_cast<uint2*>(OA + (size_t)nlo*CH + c0) = pack_h4(loA);
                    if (ph)
                        *reinterpret_cast<uint2*>(g_vh + (size_t)nlo*CH + c0) = pack_h4(loB);
                    else
                        *reinterpret_cast<float4*>(g_skip + (size_t)nlo*CH + c0) = loB;
                }
                if (nhi < NN){
                    *reinterpret_cast<uint2*>(OA + (size_t)nhi*CH + c0) = pack_h4(hiA);
                    if (ph)
                        *reinterpret_cast<uint2*>(g_vh + (size_t)nhi*CH + c0) = pack_h4(hiB);
                    else
                        *reinterpret_cast<float4*>(g_skip + (size_t)nhi*CH + c0) = hiB;
                }
            }
        }
    }
}

// ---------------------------------------------------------------------------
// fused edge pass, 8 lanes/edge, fp16 q/k/v + fp16 agg RED.
// Per edge L2 sectors: 12 read + 4 agg-RED + 1 den vs 12+8+1 before.
// ---------------------------------------------------------------------------
__global__ void k_edge(const void* __restrict__ ei_raw){
    const int gt  = blockIdx.x*blockDim.x + threadIdx.x;
    const int e   = gt >> 3;
    const int sub = threadIdx.x & 7;

    int src, dst;
    if (g_idx64){
        const long long* ei = (const long long*)ei_raw;
        src = (int)__ldg(ei + e);
        dst = (int)__ldg(ei + NE + e);
    } else {
        const int* ei = (const int*)ei_raw;
        src = __ldg(ei + e);
        dst = __ldg(ei + NE + e);
    }
    src = min(max(src, 0), NN-1);
    dst = min(max(dst, 0), NN-1);

    const uint4* qp = reinterpret_cast<const uint4*>(g_qh) + (size_t)dst*8 + sub;
    const uint4* kp = reinterpret_cast<const uint4*>(g_kh) + (size_t)src*8 + sub;
    const uint4* vp = reinterpret_cast<const uint4*>(g_vh) + (size_t)src*8 + sub;

    uint4 qr = *qp;                    // 8 halves (8 channels)
    uint4 kr = *kp;
    uint4 vr = *vp;

    float d = 0.f;
    #pragma unroll
    for (int j = 0; j < 4; j++){
        float2 qf = __half22float2(reinterpret_cast<const __half2*>(&qr)[j]);
        float2 kf = __half22float2(reinterpret_cast<const __half2*>(&kr)[j]);
        d += qf.x*kf.x + qf.y*kf.y;
    }
    d += __shfl_xor_sync(0xffffffffu, d, 4);
    d += __shfl_xor_sync(0xffffffffu, d, 2);
    d += __shfl_xor_sync(0xffffffffu, d, 1);
    const float ex = __expf(d * 0.125f);   // 1/sqrt(64)

    if (sub == 0) atomicAdd(g_den + dst, ex);

    // products in fp32, single rounding to fp16, RED.f16x2 (return unused)
    __half2* ap = reinterpret_cast<__half2*>(g_agg) + (size_t)dst*32 + sub*4;
    #pragma unroll
    for (int j = 0; j < 4; j++){
        float2 vf = __half22float2(reinterpret_cast<const __half2*>(&vr)[j]);
        atomicAdd(ap + j, __floats2half2_rn(ex*vf.x, ex*vf.y));
    }
}

// ---------------------------------------------------------------------------
// out_pre = agg/(den+1e-16) + skip ; global sum/sumsq
// thread handles 8 channels: one uint4 of fp16 agg, two float4 skip/out.
// ---------------------------------------------------------------------------
__global__ void k_final1(float* __restrict__ out){
    float lsum = 0.f, lsq = 0.f;
    const uint4*  agg8  = reinterpret_cast<const uint4*>(g_agg);
    const float4* skip4 = reinterpret_cast<const float4*>(g_skip);
    float4* out4 = reinterpret_cast<float4*>(out);
    for (int i = blockIdx.x*blockDim.x + threadIdx.x; i < NN*8;
         i += gridDim.x*blockDim.x){
        uint4 a8 = agg8[i];
        float4 s0 = skip4[2*i], s1 = skip4[2*i+1];
        const float inv = 1.f / (g_den[i>>3] + 1e-16f);
        float2 a0 = __half22float2(reinterpret_cast<const __half2*>(&a8)[0]);
        float2 a1 = __half22float2(reinterpret_cast<const __half2*>(&a8)[1]);
        float2 a2 = __half22float2(reinterpret_cast<const __half2*>(&a8)[2]);
        float2 a3 = __half22float2(reinterpret_cast<const __half2*>(&a8)[3]);
        float4 v0, v1;
        v0.x = a0.x*inv + s0.x;  v0.y = a0.y*inv + s0.y;
        v0.z = a1.x*inv + s0.z;  v0.w = a1.y*inv + s0.w;
        v1.x = a2.x*inv + s1.x;  v1.y = a2.y*inv + s1.y;
        v1.z = a3.x*inv + s1.z;  v1.w = a3.y*inv + s1.w;
        out4[2*i]   = v0;
        out4[2*i+1] = v1;
        lsum += v0.x + v0.y + v0.z + v0.w + v1.x + v1.y + v1.z + v1.w;
        lsq  += v0.x*v0.x + v0.y*v0.y + v0.z*v0.z + v0.w*v0.w
              + v1.x*v1.x + v1.y*v1.y + v1.z*v1.z + v1.w*v1.w;
    }
    #pragma unroll
    for (int off=16; off>0; off>>=1){
        lsum += __shfl_xor_sync(0xffffffffu, lsum, off);
        lsq  += __shfl_xor_sync(0xffffffffu, lsq,  off);
    }
    __shared__ float s1m[8], s2m[8];
    const int wid = threadIdx.x >> 5;
    if ((threadIdx.x & 31) == 0){ s1m[wid] = lsum; s2m[wid] = lsq; }
    __syncthreads();
    if (threadIdx.x == 0){
        float ts = 0.f, tq = 0.f;
        #pragma unroll
        for (int i=0;i<8;i++){ ts += s1m[i]; tq += s2m[i]; }
        atomicAdd(&g_red[0], (double)ts);
        atomicAdd(&g_red[1], (double)tq);
    }
}

// ---------------------------------------------------------------------------
// graph layernorm + relu
// ---------------------------------------------------------------------------
__global__ void k_final2(float* __restrict__ out,
                         const float* __restrict__ lnw,
                         const float* __restrict__ lnb){
    const int i = blockIdx.x*blockDim.x + threadIdx.x;
    if (i >= NN*16) return;
    const double invM = 1.0 / (double)(NN*CH);
    const float mean = (float)(g_red[0]*invM);
    const float var  = (float)(g_red[1]*invM) - mean*mean;
    const float rstd = 1.f / (sqrtf(fmaxf(var, 0.f)) + 1e-5f);
    const int cb = (i & 15) * 4;
    const float4 wv = *reinterpret_cast<const float4*>(lnw + cb);
    const float4 bv = *reinterpret_cast<const float4*>(lnb + cb);
    float4 x = reinterpret_cast<float4*>(out)[i];
    float4 y;
    y.x = fmaxf((x.x - mean)*rstd*wv.x + bv.x, 0.f);
    y.y = fmaxf((x.y - mean)*rstd*wv.y + bv.y, 0.f);
    y.z = fmaxf((x.z - mean)*rstd*wv.z + bv.z, 0.f);
    y.w = fmaxf((x.w - mean)*rstd*wv.w + bv.w, 0.f);
    reinterpret_cast<float4*>(out)[i] = y;
}

// ---------------------------------------------------------------------------
extern "C" void kernel_launch(void* const* d_in, const int* in_sizes, int n_in,
                              void* d_out, int out_size){
    const float* geo = (const float*)d_in[0];
    const float* euc = (const float*)d_in[1];
    const float* Wq  = (const float*)d_in[2];
    const float* bq  = (const float*)d_in[3];
    const float* Wk  = (const float*)d_in[4];
    const float* bk  = (const float*)d_in[5];
    const float* Wv  = (const float*)d_in[6];
    const float* bv  = (const float*)d_in[7];
    const float* Ws  = (const float*)d_in[8];
    const float* bs  = (const float*)d_in[9];
    const float* lnw = (const float*)d_in[10];
    const float* lnb = (const float*)d_in[11];

    const void* ei = d_in[12];
    for (int i = 0; i < n_in; i++)
        if (in_sizes[i] == 2*NE){ ei = d_in[i]; break; }

    float* out = (float*)d_out;

    cudaFuncSetAttribute(k_qkvs, cudaFuncAttributeMaxDynamicSharedMemorySize,
                         QKV_SMEM_BYTES);

    k_zero   <<<NN*16/256, 256>>>();
    k_detect <<<1, 32>>>((const unsigned int*)ei);
    k_qkvs   <<<296, 256, QKV_SMEM_BYTES>>>(geo, euc, Wq, Wk, Wv, Ws,
                                            bq, bk, bv, bs);
    k_edge   <<<NE*8/256, 256>>>(ei);
    k_final1 <<<592, 256>>>(out);
    k_final2 <<<(NN*16 + 255)/256, 256>>>(out, lnw, lnb);
}

// round 11
// speedup vs baseline: 1.5711x; 1.5711x over previous
#include <cuda_runtime.h>
#include <cuda_fp16.h>

#define NN 100000
#define NE 1600000
#define CH 64
#define NT 128                 // nodes per qkvs tile
#define NTILES 782             // ceil(NN/NT)
#define WMAT 4416              // floats per matrix in w_s (64*68 + skew pad)
#define XSZ  8512              // x tile floats (64*132 + skew pad)

typedef unsigned long long ull;

// Scratch (device globals — no allocation allowed)
__device__ __align__(16) __half g_qh[NN*CH];   // fp16 q
__device__ __align__(16) __half g_kh[NN*CH];   // fp16 k
__device__ __align__(16) __half g_vh[NN*CH];   // fp16 v
__device__ __align__(16) __half g_agg[NN*CH];  // fp16 accumulator
__device__ __align__(16) float g_skip[NN*CH];
__device__ float g_den[NN];
__device__ double g_red[2];
__device__ int g_idx64;

__device__ __forceinline__ ull ffma2(ull a, ull b, ull c){
    ull d;
    asm("fma.rn.f32x2 %0, %1, %2, %3;" : "=l"(d) : "l"(a), "l"(b), "l"(c));
    return d;
}
__device__ __forceinline__ ull splat2(float f){
    ull r;
    asm("mov.b64 %0, {%1, %1};" : "=l"(r) : "f"(f));
    return r;
}
__device__ __forceinline__ void unpack2(ull a, float& lo, float& hi){
    asm("mov.b64 {%0, %1}, %2;" : "=f"(lo), "=f"(hi) : "l"(a));
}
__device__ __forceinline__ uint2 pack_h4(float4 f){
    __half2 a01 = __floats2half2_rn(f.x, f.y);
    __half2 a23 = __floats2half2_rn(f.z, f.w);
    uint2 u;
    u.x = *reinterpret_cast<unsigned*>(&a01);
    u.y = *reinterpret_cast<unsigned*>(&a23);
    return u;
}
__device__ __forceinline__ unsigned packmul_h2(float s, float2 v){
    __half2 h = __floats2half2_rn(s*v.x, s*v.y);
    return *reinterpret_cast<unsigned*>(&h);
}

// ---------------------------------------------------------------------------
// zero accumulators + reduction cells
// ---------------------------------------------------------------------------
__global__ void k_zero(){
    int i = blockIdx.x*blockDim.x + threadIdx.x;
    if (i < NN*8)              // agg: NN*CH halves = NN*8 uint4
        reinterpret_cast<uint4*>(g_agg)[i] = make_uint4(0u,0u,0u,0u);
    if (i < NN/4)
        reinterpret_cast<float4*>(g_den)[i] = make_float4(0.f,0.f,0.f,0.f);
    if (i == 0){ g_red[0] = 0.0; g_red[1] = 0.0; }
}

// ---------------------------------------------------------------------------
// detect dtype of edge_index (int64 vs int32), 1 warp
// ---------------------------------------------------------------------------
__global__ void k_detect(const unsigned int* __restrict__ ei32){
    unsigned int hi = ei32[2*threadIdx.x + 1];
    unsigned int b = __ballot_sync(0xffffffffu, hi != 0u);
    if (threadIdx.x == 0) g_idx64 = (b == 0u);
}

// ---------------------------------------------------------------------------
// qkvs: register-tiled GEMM (4ch x 8node x 2mat = 64 fp32 acc / thread),
// skewed smem. Outputs: q,k,v -> fp16 ; skip -> fp32.
// ---------------------------------------------------------------------------
#define QKV_SMEM_BYTES ((4*WMAT + XSZ + 256)*4)

__global__ void __launch_bounds__(256, 2) k_qkvs(
    const float* __restrict__ geo, const float* __restrict__ euc,
    const float* __restrict__ Wq, const float* __restrict__ Wk,
    const float* __restrict__ Wv, const float* __restrict__ Wsk,
    const float* __restrict__ bq, const float* __restrict__ bk,
    const float* __restrict__ bv, const float* __restrict__ bsk)
{
    extern __shared__ float sm[];
    float* w_s = sm;                       // [4][WMAT]  w[m][kk][c] skewed
    float* x_s = sm + 4*WMAT;              // [XSZ]      x[kk][nl]   skewed
    float* b_s = x_s + XSZ;                // [4][64]

    const int tid = threadIdx.x;

    // stage W transposed+skewed (one-time)
    {
        const float4* Wsrc[4] = {(const float4*)Wq, (const float4*)Wk,
                                 (const float4*)Wv, (const float4*)Wsk};
        #pragma unroll
        for (int j = 0; j < 16; j++){
            int f = j*256 + tid;           // 0..4095
            int m = f >> 10, r = f & 1023;
            int c = r >> 4, kc = r & 15;
            float4 v = Wsrc[m][c*16 + kc];
            float* wb = w_s + m*WMAT + 276*kc + c;
            wb[0]   = v.x;
            wb[68]  = v.y;
            wb[136] = v.z;
            wb[204] = v.w;
        }
        if (tid < 64){
            b_s[tid]       = bq[tid];
            b_s[64 + tid]  = bk[tid];
            b_s[128 + tid] = bv[tid];
            b_s[192 + tid] = bsk[tid];
        }
    }

    const int cg = tid >> 4;               // 0..15 -> c0 = 4*cg
    const int ng = tid & 15;               // 0..15 -> n0 = 8*ng
    const int c0 = cg*4;

    #pragma unroll 1
    for (int t = blockIdx.x; t < NTILES; t += gridDim.x){
        const int base = t*NT;
        #pragma unroll 1
        for (int ph = 0; ph < 2; ph++){
            const float* X = ph ? geo : euc;
            const int mA = ph ? 1 : 0;      // k : q   (fp16 out)
            const int mB = ph ? 2 : 3;      // v : skip
            __half* OA   = ph ? g_kh : g_qh;

            __syncthreads();                // x_s free from previous readers
            #pragma unroll
            for (int j = 0; j < 8; j++){
                int f = j*256 + tid;        // 0..2047
                int nl = f >> 4;            // 0..127
                int kc = f & 15;
                int node = min(base + nl, NN-1);
                float4 v = *reinterpret_cast<const float4*>(
                    X + (size_t)node*CH + kc*4);
                float* xb = x_s + 532*kc + nl;
                xb[0]   = v.x;
                xb[132] = v.y;
                xb[264] = v.z;
                xb[396] = v.w;
            }
            __syncthreads();

            ull acc[2][4][4];
            #pragma unroll
            for (int a = 0; a < 2; a++)
                #pragma unroll
                for (int b = 0; b < 4; b++)
                    #pragma unroll
                    for (int c = 0; c < 4; c++) acc[a][b][c] = 0ull;

            const float* wArow = w_s + mA*WMAT + c0;
            const float* wBrow = w_s + mB*WMAT + c0;
            const float* xrow  = x_s + ng*8;

            #pragma unroll 8
            for (int kk = 0; kk < 64; kk++){
                const int xo = kk*132 + (kk>>2)*4;
                const int wo = kk*68  + (kk>>2)*4;
                ulonglong2 xa = *reinterpret_cast<const ulonglong2*>(xrow + xo);
                ulonglong2 xb = *reinterpret_cast<const ulonglong2*>(xrow + xo + 4);
                float4 wA = *reinterpret_cast<const float4*>(wArow + wo);
                float4 wB = *reinterpret_cast<const float4*>(wBrow + wo);
                #pragma unroll
                for (int ci = 0; ci < 4; ci++){
                    ull sA = splat2((&wA.x)[ci]);
                    acc[0][ci][0] = ffma2(xa.x, sA, acc[0][ci][0]);
                    acc[0][ci][1] = ffma2(xa.y, sA, acc[0][ci][1]);
                    acc[0][ci][2] = ffma2(xb.x, sA, acc[0][ci][2]);
                    acc[0][ci][3] = ffma2(xb.y, sA, acc[0][ci][3]);
                }
                #pragma unroll
                for (int ci = 0; ci < 4; ci++){
                    ull sB = splat2((&wB.x)[ci]);
                    acc[1][ci][0] = ffma2(xa.x, sB, acc[1][ci][0]);
                    acc[1][ci][1] = ffma2(xa.y, sB, acc[1][ci][1]);
                    acc[1][ci][2] = ffma2(xb.x, sB, acc[1][ci][2]);
                    acc[1][ci][3] = ffma2(xb.y, sB, acc[1][ci][3]);
                }
            }

            // epilogue: bias; A -> fp16; B -> fp16 (v) or fp32 (skip)
            float biasA[4], biasB[4];
            #pragma unroll
            for (int ci = 0; ci < 4; ci++){
                biasA[ci] = b_s[mA*64 + c0 + ci];
                biasB[ci] = b_s[mB*64 + c0 + ci];
            }
            const int n0 = base + ng*8;
            #pragma unroll
            for (int np = 0; np < 4; np++){
                float4 loA, hiA, loB, hiB;
                #pragma unroll
                for (int ci = 0; ci < 4; ci++){
                    float lo, hi;
                    unpack2(acc[0][ci][np], lo, hi);
                    (&loA.x)[ci] = lo + biasA[ci];
                    (&hiA.x)[ci] = hi + biasA[ci];
                    unpack2(acc[1][ci][np], lo, hi);
                    (&loB.x)[ci] = lo + biasB[ci];
                    (&hiB.x)[ci] = hi + biasB[ci];
                }
                const int nlo = n0 + 2*np, nhi = n0 + 2*np + 1;
                if (nlo < NN){
                    *reinterpret_cast<uint2*>(OA + (size_t)nlo*CH + c0) = pack_h4(loA);
                    if (ph)
                        *reinterpret_cast<uint2*>(g_vh + (size_t)nlo*CH + c0) = pack_h4(loB);
                    else
                        *reinterpret_cast<float4*>(g_skip + (size_t)nlo*CH + c0) = loB;
                }
                if (nhi < NN){
                    *reinterpret_cast<uint2*>(OA + (size_t)nhi*CH + c0) = pack_h4(hiA);
                    if (ph)
                        *reinterpret_cast<uint2*>(g_vh + (size_t)nhi*CH + c0) = pack_h4(hiB);
                    else
                        *reinterpret_cast<float4*>(g_skip + (size_t)nhi*CH + c0) = hiB;
                }
            }
        }
    }
}

// ---------------------------------------------------------------------------
// fused edge pass, 8 lanes/edge, fp16 q/k/v + ONE red.global.add.noftz.
// v4.f16x2 per lane (8 halves, 16B, single L2 atomic op).
// Per edge L2 sectors: 12 read + 4 RED + 1 den.
// ---------------------------------------------------------------------------
__global__ void k_edge(const void* __restrict__ ei_raw){
    const int gt  = blockIdx.x*blockDim.x + threadIdx.x;
    const int e   = gt >> 3;
    const int sub = threadIdx.x & 7;

    int src, dst;
    if (g_idx64){
        const long long* ei = (const long long*)ei_raw;
        src = (int)__ldg(ei + e);
        dst = (int)__ldg(ei + NE + e);
    } else {
        const int* ei = (const int*)ei_raw;
        src = __ldg(ei + e);
        dst = __ldg(ei + NE + e);
    }
    src = min(max(src, 0), NN-1);
    dst = min(max(dst, 0), NN-1);

    const uint4* qp = reinterpret_cast<const uint4*>(g_qh) + (size_t)dst*8 + sub;
    const uint4* kp = reinterpret_cast<const uint4*>(g_kh) + (size_t)src*8 + sub;
    const uint4* vp = reinterpret_cast<const uint4*>(g_vh) + (size_t)src*8 + sub;

    uint4 qr = *qp;                    // 8 halves (8 channels)
    uint4 kr = *kp;
    uint4 vr = *vp;

    float d = 0.f;
    #pragma unroll
    for (int j = 0; j < 4; j++){
        float2 qf = __half22float2(reinterpret_cast<const __half2*>(&qr)[j]);
        float2 kf = __half22float2(reinterpret_cast<const __half2*>(&kr)[j]);
        d += qf.x*kf.x + qf.y*kf.y;
    }
    d += __shfl_xor_sync(0xffffffffu, d, 4);
    d += __shfl_xor_sync(0xffffffffu, d, 2);
    d += __shfl_xor_sync(0xffffffffu, d, 1);
    const float ex = __expf(d * 0.125f);   // 1/sqrt(64)

    if (sub == 0) atomicAdd(g_den + dst, ex);

    // products in fp32, single rounding to fp16, ONE 16B vector reduction
    unsigned p0 = packmul_h2(ex, __half22float2(reinterpret_cast<const __half2*>(&vr)[0]));
    unsigned p1 = packmul_h2(ex, __half22float2(reinterpret_cast<const __half2*>(&vr)[1]));
    unsigned p2 = packmul_h2(ex, __half22float2(reinterpret_cast<const __half2*>(&vr)[2]));
    unsigned p3 = packmul_h2(ex, __half22float2(reinterpret_cast<const __half2*>(&vr)[3]));
    __half* ap = g_agg + (size_t)dst*CH + sub*8;
    asm volatile("red.global.add.noftz.v4.f16x2 [%0], {%1, %2, %3, %4};"
        :: "l"(ap), "r"(p0), "r"(p1), "r"(p2), "r"(p3) : "memory");
}

// ---------------------------------------------------------------------------
// out_pre = agg/(den+1e-16) + skip ; global sum/sumsq
// ---------------------------------------------------------------------------
__global__ void k_final1(float* __restrict__ out){
    float lsum = 0.f, lsq = 0.f;
    const uint4*  agg8  = reinterpret_cast<const uint4*>(g_agg);
    const float4* skip4 = reinterpret_cast<const float4*>(g_skip);
    float4* out4 = reinterpret_cast<float4*>(out);
    for (int i = blockIdx.x*blockDim.x + threadIdx.x; i < NN*8;
         i += gridDim.x*blockDim.x){
        uint4 a8 = agg8[i];
        float4 s0 = skip4[2*i], s1 = skip4[2*i+1];
        const float inv = 1.f / (g_den[i>>3] + 1e-16f);
        float2 a0 = __half22float2(reinterpret_cast<const __half2*>(&a8)[0]);
        float2 a1 = __half22float2(reinterpret_cast<const __half2*>(&a8)[1]);
        float2 a2 = __half22float2(reinterpret_cast<const __half2*>(&a8)[2]);
        float2 a3 = __half22float2(reinterpret_cast<const __half2*>(&a8)[3]);
        float4 v0, v1;
        v0.x = a0.x*inv + s0.x;  v0.y = a0.y*inv + s0.y;
        v0.z = a1.x*inv + s0.z;  v0.w = a1.y*inv + s0.w;
        v1.x = a2.x*inv + s1.x;  v1.y = a2.y*inv + s1.y;
        v1.z = a3.x*inv + s1.z;  v1.w = a3.y*inv + s1.w;
        out4[2*i]   = v0;
        out4[2*i+1] = v1;
        lsum += v0.x + v0.y + v0.z + v0.w + v1.x + v1.y + v1.z + v1.w;
        lsq  += v0.x*v0.x + v0.y*v0.y + v0.z*v0.z + v0.w*v0.w
              + v1.x*v1.x + v1.y*v1.y + v1.z*v1.z + v1.w*v1.w;
    }
    #pragma unroll
    for (int off=16; off>0; off>>=1){
        lsum += __shfl_xor_sync(0xffffffffu, lsum, off);
        lsq  += __shfl_xor_sync(0xffffffffu, lsq,  off);
    }
    __shared__ float s1m[8], s2m[8];
    const int wid = threadIdx.x >> 5;
    if ((threadIdx.x & 31) == 0){ s1m[wid] = lsum; s2m[wid] = lsq; }
    __syncthreads();
    if (threadIdx.x == 0){
        float ts = 0.f, tq = 0.f;
        #pragma unroll
        for (int i=0;i<8;i++){ ts += s1m[i]; tq += s2m[i]; }
        atomicAdd(&g_red[0], (double)ts);
        atomicAdd(&g_red[1], (double)tq);
    }
}

// ---------------------------------------------------------------------------
// graph layernorm + relu
// ---------------------------------------------------------------------------
__global__ void k_final2(float* __restrict__ out,
                         const float* __restrict__ lnw,
                         const float* __restrict__ lnb){
    const int i = blockIdx.x*blockDim.x + threadIdx.x;
    if (i >= NN*16) return;
    const double invM = 1.0 / (double)(NN*CH);
    const float mean = (float)(g_red[0]*invM);
    const float var  = (float)(g_red[1]*invM) - mean*mean;
    const float rstd = 1.f / (sqrtf(fmaxf(var, 0.f)) + 1e-5f);
    const int cb = (i & 15) * 4;
    const float4 wv = *reinterpret_cast<const float4*>(lnw + cb);
    const float4 bv = *reinterpret_cast<const float4*>(lnb + cb);
    float4 x = reinterpret_cast<float4*>(out)[i];
    float4 y;
    y.x = fmaxf((x.x - mean)*rstd*wv.x + bv.x, 0.f);
    y.y = fmaxf((x.y - mean)*rstd*wv.y + bv.y, 0.f);
    y.z = fmaxf((x.z - mean)*rstd*wv.z + bv.z, 0.f);
    y.w = fmaxf((x.w - mean)*rstd*wv.w + bv.w, 0.f);
    reinterpret_cast<float4*>(out)[i] = y;
}

// ---------------------------------------------------------------------------
extern "C" void kernel_launch(void* const* d_in, const int* in_sizes, int n_in,
                              void* d_out, int out_size){
    const float* geo = (const float*)d_in[0];
    const float* euc = (const float*)d_in[1];
    const float* Wq  = (const float*)d_in[2];
    const float* bq  = (const float*)d_in[3];
    const float* Wk  = (const float*)d_in[4];
    const float* bk  = (const float*)d_in[5];
    const float* Wv  = (const float*)d_in[6];
    const float* bv  = (const float*)d_in[7];
    const float* Ws  = (const float*)d_in[8];
    const float* bs  = (const float*)d_in[9];
    const float* lnw = (const float*)d_in[10];
    const float* lnb = (const float*)d_in[11];

    const void* ei = d_in[12];
    for (int i = 0; i < n_in; i++)
        if (in_sizes[i] == 2*NE){ ei = d_in[i]; break; }

    float* out = (float*)d_out;

    cudaFuncSetAttribute(k_qkvs, cudaFuncAttributeMaxDynamicSharedMemorySize,
                         QKV_SMEM_BYTES);

    k_zero   <<<NN*16/256, 256>>>();
    k_detect <<<1, 32>>>((const unsigned int*)ei);
    k_qkvs   <<<296, 256, QKV_SMEM_BYTES>>>(geo, euc, Wq, Wk, Wv, Ws,
                                            bq, bk, bv, bs);
    k_edge   <<<NE*8/256, 256>>>(ei);
    k_final1 <<<592, 256>>>(out);
    k_final2 <<<(NN*16 + 255)/256, 256>>>(out, lnw, lnb);
}

// round 12
// speedup vs baseline: 1.9888x; 1.2659x over previous
#include <cuda_runtime.h>
#include <cuda_fp16.h>

#define NN 100000
#define NE 1600000
#define CH 64

typedef unsigned long long ull;

// Scratch (device globals — no allocation allowed)
__device__ __align__(16) __half g_qh[NN*CH];   // fp16 q
__device__ __align__(16) __half g_kh[NN*CH];   // fp16 k
__device__ __align__(16) __half g_vh[NN*CH];   // fp16 v
__device__ __align__(16) __half g_agg[NN*CH];  // fp16 accumulator
__device__ __align__(16) float g_skip[NN*CH];
__device__ float g_den[NN];
__device__ double g_red[2];
__device__ int g_idx64;

__device__ __forceinline__ unsigned packh2(float a, float b){
    __half2 h = __floats2half2_rn(a, b);
    return *reinterpret_cast<unsigned*>(&h);
}
__device__ __forceinline__ unsigned packmul_h2(float s, float2 v){
    return packh2(s*v.x, s*v.y);
}

// ---------------------------------------------------------------------------
// zero accumulators (split so k_qkvs lands as the 4th launch -> ncu capture)
// ---------------------------------------------------------------------------
__global__ void k_zero_agg(){
    int i = blockIdx.x*blockDim.x + threadIdx.x;   // NN*8 uint4 of halves
    reinterpret_cast<uint4*>(g_agg)[i] = make_uint4(0u,0u,0u,0u);
}
__global__ void k_zero_den(){
    int i = blockIdx.x*blockDim.x + threadIdx.x;
    if (i < NN/4)
        reinterpret_cast<float4*>(g_den)[i] = make_float4(0.f,0.f,0.f,0.f);
    if (i == 0){ g_red[0] = 0.0; g_red[1] = 0.0; }
}

// ---------------------------------------------------------------------------
// detect dtype of edge_index (int64 vs int32), 1 warp
// ---------------------------------------------------------------------------
__global__ void k_detect(const unsigned int* __restrict__ ei32){
    unsigned int hi = ei32[2*threadIdx.x + 1];
    unsigned int b = __ballot_sync(0xffffffffu, hi != 0u);
    if (threadIdx.x == 0) g_idx64 = (b == 0u);
}

// ---------------------------------------------------------------------------
// qkvs v9: tensor-core GEMM (mma.sync.m16n8k16, fp16 in / fp32 accum).
// 8 warps: warp = (matrix m = w&3, node-half = w>>2). Warp tile M16 N64 K64.
// B = W^T fragments register-resident (loaded once per CTA); A via ldmatrix
// from a 32-node fp16 x-tile staged in smem. grid 625 x 5 tiles = 100000.
// ---------------------------------------------------------------------------
__global__ void __launch_bounds__(256, 1) k_qkvs(
    const float* __restrict__ geo, const float* __restrict__ euc,
    const float* __restrict__ Wq, const float* __restrict__ Wk,
    const float* __restrict__ Wv, const float* __restrict__ Wsk,
    const float* __restrict__ bq, const float* __restrict__ bk,
    const float* __restrict__ bv, const float* __restrict__ bsk)
{
    __shared__ __half x_s[2][32][72];   // [src][node][ch], 72-half pitch

    const int tid  = threadIdx.x;
    const int wid  = tid >> 5;
    const int lane = tid & 31;
    const int m    = wid & 3;           // 0=q 1=k 2=v 3=skip
    const int half = wid >> 2;          // 0 or 1 (16-node half)
    const int src  = (m == 1 || m == 2) ? 1 : 0;   // k,v <- geo; q,skip <- euc

    const float* W  = (m==0)?Wq:(m==1)?Wk:(m==2)?Wv:Wsk;
    const float* Bv = (m==0)?bq:(m==1)?bk:(m==2)?bv:bsk;

    const int bn  = lane >> 2;          // n-in-8 for B/C frags
    const int bk2 = (lane & 3) * 2;     // k/col-in-16 pair base

    // B fragments: [k-tile t][n-tile j][2]  (B[k][n] = W[n][k], fp32 -> fp16)
    unsigned bf[4][8][2];
    #pragma unroll
    for (int t = 0; t < 4; t++)
        #pragma unroll
        for (int j = 0; j < 8; j++){
            const float* wr = W + (8*j + bn)*CH + 16*t + bk2;
            float2 w0 = *reinterpret_cast<const float2*>(wr);
            float2 w1 = *reinterpret_cast<const float2*>(wr + 8);
            bf[t][j][0] = packh2(w0.x, w0.y);
            bf[t][j][1] = packh2(w1.x, w1.y);
        }
    // bias pairs per n-tile (cols 8j + bk2, +1)
    float2 bias[8];
    #pragma unroll
    for (int j = 0; j < 8; j++){
        bias[j].x = __ldg(Bv + 8*j + bk2);
        bias[j].y = __ldg(Bv + 8*j + bk2 + 1);
    }

    #pragma unroll 1
    for (int it = 0; it < 5; it++){
        const int base = (blockIdx.x*5 + it) * 32;

        __syncthreads();                 // x_s free from previous readers
        // stage 32 nodes x 64 ch x 2 sources, fp32 -> fp16
        #pragma unroll
        for (int s = 0; s < 2; s++){
            const float* X = s ? geo : euc;
            #pragma unroll
            for (int i = 0; i < 2; i++){
                int idx = i*256 + tid;          // 0..511
                int nl = idx >> 4, ch = idx & 15;
                float4 v = __ldg(reinterpret_cast<const float4*>(
                    X + (size_t)(base + nl)*CH + ch*4));
                uint2 u;
                u.x = packh2(v.x, v.y);
                u.y = packh2(v.z, v.w);
                *reinterpret_cast<uint2*>(&x_s[s][nl][ch*4]) = u;
            }
        }
        __syncthreads();

        // A fragments via ldmatrix.x4: rows = half*16 + (lane&15),
        // col-chunk = (lane>>4)*8 within each 16-wide k-tile
        unsigned af[4][4];
        {
            const int arow = half*16 + (lane & 15);
            const int acol = (lane >> 4) * 8;
            #pragma unroll
            for (int t = 0; t < 4; t++){
                unsigned addr = (unsigned)__cvta_generic_to_shared(
                    &x_s[src][arow][16*t + acol]);
                asm volatile(
                    "ldmatrix.sync.aligned.m8n8.x4.shared.b16 {%0,%1,%2,%3}, [%4];"
                    : "=r"(af[t][0]), "=r"(af[t][1]), "=r"(af[t][2]), "=r"(af[t][3])
                    : "r"(addr));
            }
        }

        float cf[8][4];
        #pragma unroll
        for (int j = 0; j < 8; j++)
            #pragma unroll
            for (int c = 0; c < 4; c++) cf[j][c] = 0.f;

        #pragma unroll
        for (int t = 0; t < 4; t++)
            #pragma unroll
            for (int j = 0; j < 8; j++){
                asm volatile(
                    "mma.sync.aligned.m16n8k16.row.col.f32.f16.f16.f32 "
                    "{%0,%1,%2,%3}, {%4,%5,%6,%7}, {%8,%9}, {%0,%1,%2,%3};"
                    : "+f"(cf[j][0]), "+f"(cf[j][1]), "+f"(cf[j][2]), "+f"(cf[j][3])
                    : "r"(af[t][0]), "r"(af[t][1]), "r"(af[t][2]), "r"(af[t][3]),
                      "r"(bf[t][j][0]), "r"(bf[t][j][1]));
            }

        // epilogue: c0,c1 -> row r0, cols 8j+bk2,+1 ; c2,c3 -> row r0+8
        const int r0 = base + half*16 + (lane >> 2);
        if (m == 3){
            #pragma unroll
            for (int j = 0; j < 8; j++){
                float2 lo = make_float2(cf[j][0] + bias[j].x, cf[j][1] + bias[j].y);
                float2 hi = make_float2(cf[j][2] + bias[j].x, cf[j][3] + bias[j].y);
                *reinterpret_cast<float2*>(g_skip + (size_t)r0*CH + 8*j + bk2) = lo;
                *reinterpret_cast<float2*>(g_skip + (size_t)(r0+8)*CH + 8*j + bk2) = hi;
            }
        } else {
            __half* O = (m==0) ? g_qh : (m==1) ? g_kh : g_vh;
            #pragma unroll
            for (int j = 0; j < 8; j++){
                unsigned lo = packh2(cf[j][0] + bias[j].x, cf[j][1] + bias[j].y);
                unsigned hi = packh2(cf[j][2] + bias[j].x, cf[j][3] + bias[j].y);
                *reinterpret_cast<unsigned*>(O + (size_t)r0*CH + 8*j + bk2) = lo;
                *reinterpret_cast<unsigned*>(O + (size_t)(r0+8)*CH + 8*j + bk2) = hi;
            }
        }
    }
}

// ---------------------------------------------------------------------------
// fused edge pass, 8 lanes/edge, fp16 q/k/v + ONE red.global.add.noftz.
// v4.f16x2 per lane (8 halves, 16B, single L2 atomic op).
// ---------------------------------------------------------------------------
__global__ void k_edge(const void* __restrict__ ei_raw){
    const int gt  = blockIdx.x*blockDim.x + threadIdx.x;
    const int e   = gt >> 3;
    const int sub = threadIdx.x & 7;

    int src, dst;
    if (g_idx64){
        const long long* ei = (const long long*)ei_raw;
        src = (int)__ldg(ei + e);
        dst = (int)__ldg(ei + NE + e);
    } else {
        const int* ei = (const int*)ei_raw;
        src = __ldg(ei + e);
        dst = __ldg(ei + NE + e);
    }
    src = min(max(src, 0), NN-1);
    dst = min(max(dst, 0), NN-1);

    const uint4* qp = reinterpret_cast<const uint4*>(g_qh) + (size_t)dst*8 + sub;
    const uint4* kp = reinterpret_cast<const uint4*>(g_kh) + (size_t)src*8 + sub;
    const uint4* vp = reinterpret_cast<const uint4*>(g_vh) + (size_t)src*8 + sub;

    uint4 qr = *qp;                    // 8 halves (8 channels)
    uint4 kr = *kp;
    uint4 vr = *vp;

    float d = 0.f;
    #pragma unroll
    for (int j = 0; j < 4; j++){
        float2 qf = __half22float2(reinterpret_cast<const __half2*>(&qr)[j]);
        float2 kf = __half22float2(reinterpret_cast<const __half2*>(&kr)[j]);
        d += qf.x*kf.x + qf.y*kf.y;
    }
    d += __shfl_xor_sync(0xffffffffu, d, 4);
    d += __shfl_xor_sync(0xffffffffu, d, 2);
    d += __shfl_xor_sync(0xffffffffu, d, 1);
    const float ex = __expf(d * 0.125f);   // 1/sqrt(64)

    if (sub == 0) atomicAdd(g_den + dst, ex);

    unsigned p0 = packmul_h2(ex, __half22float2(reinterpret_cast<const __half2*>(&vr)[0]));
    unsigned p1 = packmul_h2(ex, __half22float2(reinterpret_cast<const __half2*>(&vr)[1]));
    unsigned p2 = packmul_h2(ex, __half22float2(reinterpret_cast<const __half2*>(&vr)[2]));
    unsigned p3 = packmul_h2(ex, __half22float2(reinterpret_cast<const __half2*>(&vr)[3]));
    __half* ap = g_agg + (size_t)dst*CH + sub*8;
    asm volatile("red.global.add.noftz.v4.f16x2 [%0], {%1, %2, %3, %4};"
        :: "l"(ap), "r"(p0), "r"(p1), "r"(p2), "r"(p3) : "memory");
}

// ---------------------------------------------------------------------------
// out_pre = agg/(den+1e-16) + skip ; global sum/sumsq
// ---------------------------------------------------------------------------
__global__ void k_final1(float* __restrict__ out){
    float lsum = 0.f, lsq = 0.f;
    const uint4*  agg8  = reinterpret_cast<const uint4*>(g_agg);
    const float4* skip4 = reinterpret_cast<const float4*>(g_skip);
    float4* out4 = reinterpret_cast<float4*>(out);
    for (int i = blockIdx.x*blockDim.x + threadIdx.x; i < NN*8;
         i += gridDim.x*blockDim.x){
        uint4 a8 = agg8[i];
        float4 s0 = skip4[2*i], s1 = skip4[2*i+1];
        const float inv = 1.f / (g_den[i>>3] + 1e-16f);
        float2 a0 = __half22float2(reinterpret_cast<const __half2*>(&a8)[0]);
        float2 a1 = __half22float2(reinterpret_cast<const __half2*>(&a8)[1]);
        float2 a2 = __half22float2(reinterpret_cast<const __half2*>(&a8)[2]);
        float2 a3 = __half22float2(reinterpret_cast<const __half2*>(&a8)[3]);
        float4 v0, v1;
        v0.x = a0.x*inv + s0.x;  v0.y = a0.y*inv + s0.y;
        v0.z = a1.x*inv + s0.z;  v0.w = a1.y*inv + s0.w;
        v1.x = a2.x*inv + s1.x;  v1.y = a2.y*inv + s1.y;
        v1.z = a3.x*inv + s1.z;  v1.w = a3.y*inv + s1.w;
        out4[2*i]   = v0;
        out4[2*i+1] = v1;
        lsum += v0.x + v0.y + v0.z + v0.w + v1.x + v1.y + v1.z + v1.w;
        lsq  += v0.x*v0.x + v0.y*v0.y + v0.z*v0.z + v0.w*v0.w
              + v1.x*v1.x + v1.y*v1.y + v1.z*v1.z + v1.w*v1.w;
    }
    #pragma unroll
    for (int off=16; off>0; off>>=1){
        lsum += __shfl_xor_sync(0xffffffffu, lsum, off);
        lsq  += __shfl_xor_sync(0xffffffffu, lsq,  off);
    }
    __shared__ float s1m[8], s2m[8];
    const int wid = threadIdx.x >> 5;
    if ((threadIdx.x & 31) == 0){ s1m[wid] = lsum; s2m[wid] = lsq; }
    __syncthreads();
    if (threadIdx.x == 0){
        float ts = 0.f, tq = 0.f;
        #pragma unroll
        for (int i=0;i<8;i++){ ts += s1m[i]; tq += s2m[i]; }
        atomicAdd(&g_red[0], (double)ts);
        atomicAdd(&g_red[1], (double)tq);
    }
}

// ---------------------------------------------------------------------------
// graph layernorm + relu
// ---------------------------------------------------------------------------
__global__ void k_final2(float* __restrict__ out,
                         const float* __restrict__ lnw,
                         const float* __restrict__ lnb){
    const int i = blockIdx.x*blockDim.x + threadIdx.x;
    if (i >= NN*16) return;
    const double invM = 1.0 / (double)(NN*CH);
    const float mean = (float)(g_red[0]*invM);
    const float var  = (float)(g_red[1]*invM) - mean*mean;
    const float rstd = 1.f / (sqrtf(fmaxf(var, 0.f)) + 1e-5f);
    const int cb = (i & 15) * 4;
    const float4 wv = *reinterpret_cast<const float4*>(lnw + cb);
    const float4 bv = *reinterpret_cast<const float4*>(lnb + cb);
    float4 x = reinterpret_cast<float4*>(out)[i];
    float4 y;
    y.x = fmaxf((x.x - mean)*rstd*wv.x + bv.x, 0.f);
    y.y = fmaxf((x.y - mean)*rstd*wv.y + bv.y, 0.f);
    y.z = fmaxf((x.z - mean)*rstd*wv.z + bv.z, 0.f);
    y.w = fmaxf((x.w - mean)*rstd*wv.w + bv.w, 0.f);
    reinterpret_cast<float4*>(out)[i] = y;
}

// ---------------------------------------------------------------------------
extern "C" void kernel_launch(void* const* d_in, const int* in_sizes, int n_in,
                              void* d_out, int out_size){
    const float* geo = (const float*)d_in[0];
    const float* euc = (const float*)d_in[1];
    const float* Wq  = (const float*)d_in[2];
    const float* bq  = (const float*)d_in[3];
    const float* Wk  = (const float*)d_in[4];
    const float* bk  = (const float*)d_in[5];
    const float* Wv  = (const float*)d_in[6];
    const float* bv  = (const float*)d_in[7];
    const float* Ws  = (const float*)d_in[8];
    const float* bs  = (const float*)d_in[9];
    const float* lnw = (const float*)d_in[10];
    const float* lnb = (const float*)d_in[11];

    const void* ei = d_in[12];
    for (int i = 0; i < n_in; i++)
        if (in_sizes[i] == 2*NE){ ei = d_in[i]; break; }

    float* out = (float*)d_out;

    k_zero_agg<<<NN*8/256, 256>>>();
    k_zero_den<<<(NN/4 + 255)/256, 256>>>();
    k_detect  <<<1, 32>>>((const unsigned int*)ei);
    k_qkvs    <<<625, 256>>>(geo, euc, Wq, Wk, Wv, Ws, bq, bk, bv, bs);
    k_edge    <<<NE*8/256, 256>>>(ei);
    k_final1  <<<592, 256>>>(out);
    k_final2  <<<(NN*16 + 255)/256, 256>>>(out, lnw, lnb);
}

// round 13
// speedup vs baseline: 2.2093x; 1.1108x over previous
#include <cuda_runtime.h>
#include <cuda_fp16.h>

#define NN 100000
#define NE 1600000
#define CH 64

typedef unsigned long long ull;

// Scratch (device globals — no allocation allowed)
__device__ __align__(16) __half g_qh[NN*CH];   // fp16 q
__device__ __align__(16) __half g_kh[NN*CH];   // fp16 k
__device__ __align__(16) __half g_vh[NN*CH];   // fp16 v
__device__ __align__(16) __half g_agg[NN*CH];  // fp16 accumulator
__device__ __align__(16) float g_skip[NN*CH];
__device__ float g_den[NN];
__device__ double g_red[2];
__device__ int g_idx64;

__device__ __forceinline__ unsigned packh2(float a, float b){
    __half2 h = __floats2half2_rn(a, b);
    return *reinterpret_cast<unsigned*>(&h);
}
__device__ __forceinline__ unsigned packmul_h2(float s, float2 v){
    return packh2(s*v.x, s*v.y);
}

// ---------------------------------------------------------------------------
// zero accumulators (split so k_qkvs lands as the 4th launch -> ncu capture)
// ---------------------------------------------------------------------------
__global__ void k_zero_agg(){
    int i = blockIdx.x*blockDim.x + threadIdx.x;   // NN*8 uint4 of halves
    reinterpret_cast<uint4*>(g_agg)[i] = make_uint4(0u,0u,0u,0u);
}
__global__ void k_zero_den(){
    int i = blockIdx.x*blockDim.x + threadIdx.x;
    if (i < NN/4)
        reinterpret_cast<float4*>(g_den)[i] = make_float4(0.f,0.f,0.f,0.f);
    if (i == 0){ g_red[0] = 0.0; g_red[1] = 0.0; }
}

// ---------------------------------------------------------------------------
// detect dtype of edge_index (int64 vs int32), 1 warp
// ---------------------------------------------------------------------------
__global__ void k_detect(const unsigned int* __restrict__ ei32){
    unsigned int hi = ei32[2*threadIdx.x + 1];
    unsigned int b = __ballot_sync(0xffffffffu, hi != 0u);
    if (threadIdx.x == 0) g_idx64 = (b == 0u);
}

// ---------------------------------------------------------------------------
// qkvs v10: tensor-core GEMM (mma.sync.m16n8k16), software-pipelined.
// 8 warps: warp = (matrix m = w&3, node-half = w>>2). Warp tile M16 N64 K64.
// B = W^T fragments register-resident; x tiles double-buffered in smem with
// REGISTER PREFETCH: tile i+1's LDGs are issued right after the barrier,
// in flight during tile i's ldmatrix/mma/epilogue.
// ---------------------------------------------------------------------------
__global__ void __launch_bounds__(256, 1) k_qkvs(
    const float* __restrict__ geo, const float* __restrict__ euc,
    const float* __restrict__ Wq, const float* __restrict__ Wk,
    const float* __restrict__ Wv, const float* __restrict__ Wsk,
    const float* __restrict__ bq, const float* __restrict__ bk,
    const float* __restrict__ bv, const float* __restrict__ bsk)
{
    __shared__ __half x_s[2][2][32][72];  // [buf][src][node][ch]

    const int tid  = threadIdx.x;
    const int wid  = tid >> 5;
    const int lane = tid & 31;
    const int m    = wid & 3;           // 0=q 1=k 2=v 3=skip
    const int half = wid >> 2;          // 0 or 1 (16-node half)
    const int src  = (m == 1 || m == 2) ? 1 : 0;   // k,v <- geo; q,skip <- euc

    const float* W  = (m==0)?Wq:(m==1)?Wk:(m==2)?Wv:Wsk;
    const float* Bv = (m==0)?bq:(m==1)?bk:(m==2)?bv:bsk;

    const int bn  = lane >> 2;          // n-in-8 for B/C frags
    const int bk2 = (lane & 3) * 2;     // k/col-in-16 pair base

    // staging decomposition (per thread: 2 sources x 2 chunks = 4 LDG.128)
    const int snl = tid >> 4;           // node 0..15 (+16 for second chunk)
    const int sch = tid & 15;           // ch-quad 0..15

    // B fragments: [k-tile t][n-tile j][2]  (B[k][n] = W[n][k], fp32 -> fp16)
    unsigned bf[4][8][2];
    #pragma unroll
    for (int t = 0; t < 4; t++)
        #pragma unroll
        for (int j = 0; j < 8; j++){
            const float* wr = W + (8*j + bn)*CH + 16*t + bk2;
            float2 w0 = *reinterpret_cast<const float2*>(wr);
            float2 w1 = *reinterpret_cast<const float2*>(wr + 8);
            bf[t][j][0] = packh2(w0.x, w0.y);
            bf[t][j][1] = packh2(w1.x, w1.y);
        }
    float2 bias[8];
    #pragma unroll
    for (int j = 0; j < 8; j++){
        bias[j].x = __ldg(Bv + 8*j + bk2);
        bias[j].y = __ldg(Bv + 8*j + bk2 + 1);
    }

    // prefetch tile 0
    float4 pf[4];
    {
        const int base0 = blockIdx.x*5*32;
        pf[0] = __ldg(reinterpret_cast<const float4*>(euc + (size_t)(base0+snl)*CH    + sch*4));
        pf[1] = __ldg(reinterpret_cast<const float4*>(euc + (size_t)(base0+snl+16)*CH + sch*4));
        pf[2] = __ldg(reinterpret_cast<const float4*>(geo + (size_t)(base0+snl)*CH    + sch*4));
        pf[3] = __ldg(reinterpret_cast<const float4*>(geo + (size_t)(base0+snl+16)*CH + sch*4));
    }

    #pragma unroll 1
    for (int it = 0; it < 5; it++){
        const int base = (blockIdx.x*5 + it) * 32;
        const int buf  = it & 1;

        // store prefetched tile (fp32 -> fp16)
        {
            uint2 u;
            u.x = packh2(pf[0].x, pf[0].y); u.y = packh2(pf[0].z, pf[0].w);
            *reinterpret_cast<uint2*>(&x_s[buf][0][snl][sch*4]) = u;
            u.x = packh2(pf[1].x, pf[1].y); u.y = packh2(pf[1].z, pf[1].w);
            *reinterpret_cast<uint2*>(&x_s[buf][0][snl+16][sch*4]) = u;
            u.x = packh2(pf[2].x, pf[2].y); u.y = packh2(pf[2].z, pf[2].w);
            *reinterpret_cast<uint2*>(&x_s[buf][1][snl][sch*4]) = u;
            u.x = packh2(pf[3].x, pf[3].y); u.y = packh2(pf[3].z, pf[3].w);
            *reinterpret_cast<uint2*>(&x_s[buf][1][snl+16][sch*4]) = u;
        }
        __syncthreads();

        // issue next tile's loads immediately (in flight during compute)
        if (it < 4){
            const int nb = base + 32;
            pf[0] = __ldg(reinterpret_cast<const float4*>(euc + (size_t)(nb+snl)*CH    + sch*4));
            pf[1] = __ldg(reinterpret_cast<const float4*>(euc + (size_t)(nb+snl+16)*CH + sch*4));
            pf[2] = __ldg(reinterpret_cast<const float4*>(geo + (size_t)(nb+snl)*CH    + sch*4));
            pf[3] = __ldg(reinterpret_cast<const float4*>(geo + (size_t)(nb+snl+16)*CH + sch*4));
        }

        // A fragments via ldmatrix.x4
        unsigned af[4][4];
        {
            const int arow = half*16 + (lane & 15);
            const int acol = (lane >> 4) * 8;
            #pragma unroll
            for (int t = 0; t < 4; t++){
                unsigned addr = (unsigned)__cvta_generic_to_shared(
                    &x_s[buf][src][arow][16*t + acol]);
                asm volatile(
                    "ldmatrix.sync.aligned.m8n8.x4.shared.b16 {%0,%1,%2,%3}, [%4];"
                    : "=r"(af[t][0]), "=r"(af[t][1]), "=r"(af[t][2]), "=r"(af[t][3])
                    : "r"(addr));
            }
        }

        float cf[8][4];
        #pragma unroll
        for (int j = 0; j < 8; j++)
            #pragma unroll
            for (int c = 0; c < 4; c++) cf[j][c] = 0.f;

        #pragma unroll
        for (int t = 0; t < 4; t++)
            #pragma unroll
            for (int j = 0; j < 8; j++){
                asm volatile(
                    "mma.sync.aligned.m16n8k16.row.col.f32.f16.f16.f32 "
                    "{%0,%1,%2,%3}, {%4,%5,%6,%7}, {%8,%9}, {%0,%1,%2,%3};"
                    : "+f"(cf[j][0]), "+f"(cf[j][1]), "+f"(cf[j][2]), "+f"(cf[j][3])
                    : "r"(af[t][0]), "r"(af[t][1]), "r"(af[t][2]), "r"(af[t][3]),
                      "r"(bf[t][j][0]), "r"(bf[t][j][1]));
            }

        // epilogue
        const int r0 = base + half*16 + (lane >> 2);
        if (m == 3){
            #pragma unroll
            for (int j = 0; j < 8; j++){
                float2 lo = make_float2(cf[j][0] + bias[j].x, cf[j][1] + bias[j].y);
                float2 hi = make_float2(cf[j][2] + bias[j].x, cf[j][3] + bias[j].y);
                *reinterpret_cast<float2*>(g_skip + (size_t)r0*CH + 8*j + bk2) = lo;
                *reinterpret_cast<float2*>(g_skip + (size_t)(r0+8)*CH + 8*j + bk2) = hi;
            }
        } else {
            __half* O = (m==0) ? g_qh : (m==1) ? g_kh : g_vh;
            #pragma unroll
            for (int j = 0; j < 8; j++){
                unsigned lo = packh2(cf[j][0] + bias[j].x, cf[j][1] + bias[j].y);
                unsigned hi = packh2(cf[j][2] + bias[j].x, cf[j][3] + bias[j].y);
                *reinterpret_cast<unsigned*>(O + (size_t)r0*CH + 8*j + bk2) = lo;
                *reinterpret_cast<unsigned*>(O + (size_t)(r0+8)*CH + 8*j + bk2) = hi;
            }
        }
    }
}

// ---------------------------------------------------------------------------
// fused edge pass, 8 lanes/edge, fp16 q/k/v + ONE red.global.add.noftz.
// v4.f16x2 per lane (8 halves, 16B, single L2 atomic op).
// ---------------------------------------------------------------------------
__global__ void k_edge(const void* __restrict__ ei_raw){
    const int gt  = blockIdx.x*blockDim.x + threadIdx.x;
    const int e   = gt >> 3;
    const int sub = threadIdx.x & 7;

    int src, dst;
    if (g_idx64){
        const long long* ei = (const long long*)ei_raw;
        src = (int)__ldg(ei + e);
        dst = (int)__ldg(ei + NE + e);
    } else {
        const int* ei = (const int*)ei_raw;
        src = __ldg(ei + e);
        dst = __ldg(ei + NE + e);
    }
    src = min(max(src, 0), NN-1);
    dst = min(max(dst, 0), NN-1);

    const uint4* qp = reinterpret_cast<const uint4*>(g_qh) + (size_t)dst*8 + sub;
    const uint4* kp = reinterpret_cast<const uint4*>(g_kh) + (size_t)src*8 + sub;
    const uint4* vp = reinterpret_cast<const uint4*>(g_vh) + (size_t)src*8 + sub;

    uint4 qr = *qp;                    // 8 halves (8 channels)
    uint4 kr = *kp;
    uint4 vr = *vp;

    float d = 0.f;
    #pragma unroll
    for (int j = 0; j < 4; j++){
        float2 qf = __half22float2(reinterpret_cast<const __half2*>(&qr)[j]);
        float2 kf = __half22float2(reinterpret_cast<const __half2*>(&kr)[j]);
        d += qf.x*kf.x + qf.y*kf.y;
    }
    d += __shfl_xor_sync(0xffffffffu, d, 4);
    d += __shfl_xor_sync(0xffffffffu, d, 2);
    d += __shfl_xor_sync(0xffffffffu, d, 1);
    const float ex = __expf(d * 0.125f);   // 1/sqrt(64)

    if (sub == 0) atomicAdd(g_den + dst, ex);

    unsigned p0 = packmul_h2(ex, __half22float2(reinterpret_cast<const __half2*>(&vr)[0]));
    unsigned p1 = packmul_h2(ex, __half22float2(reinterpret_cast<const __half2*>(&vr)[1]));
    unsigned p2 = packmul_h2(ex, __half22float2(reinterpret_cast<const __half2*>(&vr)[2]));
    unsigned p3 = packmul_h2(ex, __half22float2(reinterpret_cast<const __half2*>(&vr)[3]));
    __half* ap = g_agg + (size_t)dst*CH + sub*8;
    asm volatile("red.global.add.noftz.v4.f16x2 [%0], {%1, %2, %3, %4};"
        :: "l"(ap), "r"(p0), "r"(p1), "r"(p2), "r"(p3) : "memory");
}

// ---------------------------------------------------------------------------
// out_pre = agg/(den+1e-16) + skip ; global sum/sumsq
// ---------------------------------------------------------------------------
__global__ void k_final1(float* __restrict__ out){
    float lsum = 0.f, lsq = 0.f;
    const uint4*  agg8  = reinterpret_cast<const uint4*>(g_agg);
    const float4* skip4 = reinterpret_cast<const float4*>(g_skip);
    float4* out4 = reinterpret_cast<float4*>(out);
    for (int i = blockIdx.x*blockDim.x + threadIdx.x; i < NN*8;
         i += gridDim.x*blockDim.x){
        uint4 a8 = agg8[i];
        float4 s0 = skip4[2*i], s1 = skip4[2*i+1];
        const float inv = 1.f / (g_den[i>>3] + 1e-16f);
        float2 a0 = __half22float2(reinterpret_cast<const __half2*>(&a8)[0]);
        float2 a1 = __half22float2(reinterpret_cast<const __half2*>(&a8)[1]);
        float2 a2 = __half22float2(reinterpret_cast<const __half2*>(&a8)[2]);
        float2 a3 = __half22float2(reinterpret_cast<const __half2*>(&a8)[3]);
        float4 v0, v1;
        v0.x = a0.x*inv + s0.x;  v0.y = a0.y*inv + s0.y;
        v0.z = a1.x*inv + s0.z;  v0.w = a1.y*inv + s0.w;
        v1.x = a2.x*inv + s1.x;  v1.y = a2.y*inv + s1.y;
        v1.z = a3.x*inv + s1.z;  v1.w = a3.y*inv + s1.w;
        out4[2*i]   = v0;
        out4[2*i+1] = v1;
        lsum += v0.x + v0.y + v0.z + v0.w + v1.x + v1.y + v1.z + v1.w;
        lsq  += v0.x*v0.x + v0.y*v0.y + v0.z*v0.z + v0.w*v0.w
              + v1.x*v1.x + v1.y*v1.y + v1.z*v1.z + v1.w*v1.w;
    }
    #pragma unroll
    for (int off=16; off>0; off>>=1){
        lsum += __shfl_xor_sync(0xffffffffu, lsum, off);
        lsq  += __shfl_xor_sync(0xffffffffu, lsq,  off);
    }
    __shared__ float s1m[8], s2m[8];
    const int wid = threadIdx.x >> 5;
    if ((threadIdx.x & 31) == 0){ s1m[wid] = lsum; s2m[wid] = lsq; }
    __syncthreads();
    if (threadIdx.x == 0){
        float ts = 0.f, tq = 0.f;
        #pragma unroll
        for (int i=0;i<8;i++){ ts += s1m[i]; tq += s2m[i]; }
        atomicAdd(&g_red[0], (double)ts);
        atomicAdd(&g_red[1], (double)tq);
    }
}

// ---------------------------------------------------------------------------
// graph layernorm + relu
// ---------------------------------------------------------------------------
__global__ void k_final2(float* __restrict__ out,
                         const float* __restrict__ lnw,
                         const float* __restrict__ lnb){
    const int i = blockIdx.x*blockDim.x + threadIdx.x;
    if (i >= NN*16) return;
    const double invM = 1.0 / (double)(NN*CH);
    const float mean = (float)(g_red[0]*invM);
    const float var  = (float)(g_red[1]*invM) - mean*mean;
    const float rstd = 1.f / (sqrtf(fmaxf(var, 0.f)) + 1e-5f);
    const int cb = (i & 15) * 4;
    const float4 wv = *reinterpret_cast<const float4*>(lnw + cb);
    const float4 bv = *reinterpret_cast<const float4*>(lnb + cb);
    float4 x = reinterpret_cast<float4*>(out)[i];
    float4 y;
    y.x = fmaxf((x.x - mean)*rstd*wv.x + bv.x, 0.f);
    y.y = fmaxf((x.y - mean)*rstd*wv.y + bv.y, 0.f);
    y.z = fmaxf((x.z - mean)*rstd*wv.z + bv.z, 0.f);
    y.w = fmaxf((x.w - mean)*rstd*wv.w + bv.w, 0.f);
    reinterpret_cast<float4*>(out)[i] = y;
}

// ---------------------------------------------------------------------------
extern "C" void kernel_launch(void* const* d_in, const int* in_sizes, int n_in,
                              void* d_out, int out_size){
    const float* geo = (const float*)d_in[0];
    const float* euc = (const float*)d_in[1];
    const float* Wq  = (const float*)d_in[2];
    const float* bq  = (const float*)d_in[3];
    const float* Wk  = (const float*)d_in[4];
    const float* bk  = (const float*)d_in[5];
    const float* Wv  = (const float*)d_in[6];
    const float* bv  = (const float*)d_in[7];
    const float* Ws  = (const float*)d_in[8];
    const float* bs  = (const float*)d_in[9];
    const float* lnw = (const float*)d_in[10];
    const float* lnb = (const float*)d_in[11];

    const void* ei = d_in[12];
    for (int i = 0; i < n_in; i++)
        if (in_sizes[i] == 2*NE){ ei = d_in[i]; break; }

    float* out = (float*)d_out;

    k_zero_agg<<<NN*8/256, 256>>>();
    k_zero_den<<<(NN/4 + 255)/256, 256>>>();
    k_detect  <<<1, 32>>>((const unsigned int*)ei);
    k_qkvs    <<<625, 256>>>(geo, euc, Wq, Wk, Wv, Ws, bq, bk, bv, bs);
    k_edge    <<<NE*8/256, 256>>>(ei);
    k_final1  <<<592, 256>>>(out);
    k_final2  <<<(NN*16 + 255)/256, 256>>>(out, lnw, lnb);
}

// round 14
// speedup vs baseline: 2.3092x; 1.0452x over previous
#include <cuda_runtime.h>
#include <cuda_fp16.h>

#define NN 100000
#define NE 1600000
#define CH 64
#define FGRID 148              // persistent final kernel grid (co-resident)

typedef unsigned long long ull;

// Scratch (device globals — no allocation allowed)
__device__ __align__(16) __half g_qh[NN*CH];   // fp16 q
__device__ __align__(16) __half g_kh[NN*CH];   // fp16 k
__device__ __align__(16) __half g_vh[NN*CH];   // fp16 v
__device__ __align__(16) __half g_agg[NN*CH];  // fp16 accumulator
__device__ __align__(16) float g_skip[NN*CH];
__device__ float g_den[NN];
__device__ double g_red[2];
__device__ unsigned g_bar;
__device__ int g_idx64;

__device__ __forceinline__ unsigned packh2(float a, float b){
    __half2 h = __floats2half2_rn(a, b);
    return *reinterpret_cast<unsigned*>(&h);
}
__device__ __forceinline__ unsigned packmul_h2(float s, float2 v){
    return packh2(s*v.x, s*v.y);
}

// ---------------------------------------------------------------------------
// init: zero agg/den/red/bar + detect edge-index dtype (block 0, warp 0)
// ---------------------------------------------------------------------------
__global__ void k_init(const unsigned int* __restrict__ ei32){
    int i = blockIdx.x*blockDim.x + threadIdx.x;
    if (i < NN*8)
        reinterpret_cast<uint4*>(g_agg)[i] = make_uint4(0u,0u,0u,0u);
    if (i < NN/4)
        reinterpret_cast<float4*>(g_den)[i] = make_float4(0.f,0.f,0.f,0.f);
    if (i == 0){ g_red[0] = 0.0; g_red[1] = 0.0; g_bar = 0u; }
    if (blockIdx.x == 0 && threadIdx.x < 32){
        unsigned int hi = ei32[2*threadIdx.x + 1];
        unsigned int b = __ballot_sync(0xffffffffu, hi != 0u);
        if (threadIdx.x == 0) g_idx64 = (b == 0u);
    }
}

// ---------------------------------------------------------------------------
// qkvs v11: tensor-core GEMM (mma.sync.m16n8k16), software-pipelined,
// 128-thread CTAs (4 warps = 4 matrices, 16-node tiles) -> 2 CTAs/SM.
// B = W^T fragments register-resident; x tiles double-buffered in smem with
// register prefetch. grid 1250 x 5 tiles of 16 nodes = 100000.
// ---------------------------------------------------------------------------
__global__ void __launch_bounds__(128, 2) k_qkvs(
    const float* __restrict__ geo, const float* __restrict__ euc,
    const float* __restrict__ Wq, const float* __restrict__ Wk,
    const float* __restrict__ Wv, const float* __restrict__ Wsk,
    const float* __restrict__ bq, const float* __restrict__ bk,
    const float* __restrict__ bv, const float* __restrict__ bsk)
{
    __shared__ __half x_s[2][2][16][72];  // [buf][src][node][ch]

    const int tid  = threadIdx.x;
    const int wid  = tid >> 5;
    const int lane = tid & 31;
    const int m    = wid;               // 0=q 1=k 2=v 3=skip
    const int src  = (m == 1 || m == 2) ? 1 : 0;   // k,v <- geo; q,skip <- euc

    const float* W  = (m==0)?Wq:(m==1)?Wk:(m==2)?Wv:Wsk;
    const float* Bv = (m==0)?bq:(m==1)?bk:(m==2)?bv:bsk;

    const int bn  = lane >> 2;          // n-in-8 for B/C frags
    const int bk2 = (lane & 3) * 2;     // k/col pair base

    // staging decomposition (per thread: 2 srcs x 2 node-chunks = 4 LDG.128)
    const int snl = tid >> 4;           // node 0..7 (+8 for second chunk)
    const int sch = tid & 15;           // ch-quad 0..15

    // B fragments: [k-tile t][n-tile j][2]
    unsigned bf[4][8][2];
    #pragma unroll
    for (int t = 0; t < 4; t++)
        #pragma unroll
        for (int j = 0; j < 8; j++){
            const float* wr = W + (8*j + bn)*CH + 16*t + bk2;
            float2 w0 = *reinterpret_cast<const float2*>(wr);
            float2 w1 = *reinterpret_cast<const float2*>(wr + 8);
            bf[t][j][0] = packh2(w0.x, w0.y);
            bf[t][j][1] = packh2(w1.x, w1.y);
        }
    float2 bias[8];
    #pragma unroll
    for (int j = 0; j < 8; j++){
        bias[j].x = __ldg(Bv + 8*j + bk2);
        bias[j].y = __ldg(Bv + 8*j + bk2 + 1);
    }

    // prefetch tile 0
    float4 pf[4];
    {
        const int base0 = blockIdx.x*5*16;
        pf[0] = __ldg(reinterpret_cast<const float4*>(euc + (size_t)(base0+snl)*CH   + sch*4));
        pf[1] = __ldg(reinterpret_cast<const float4*>(euc + (size_t)(base0+snl+8)*CH + sch*4));
        pf[2] = __ldg(reinterpret_cast<const float4*>(geo + (size_t)(base0+snl)*CH   + sch*4));
        pf[3] = __ldg(reinterpret_cast<const float4*>(geo + (size_t)(base0+snl+8)*CH + sch*4));
    }

    #pragma unroll 1
    for (int it = 0; it < 5; it++){
        const int base = (blockIdx.x*5 + it) * 16;
        const int buf  = it & 1;

        {
            uint2 u;
            u.x = packh2(pf[0].x, pf[0].y); u.y = packh2(pf[0].z, pf[0].w);
            *reinterpret_cast<uint2*>(&x_s[buf][0][snl][sch*4]) = u;
            u.x = packh2(pf[1].x, pf[1].y); u.y = packh2(pf[1].z, pf[1].w);
            *reinterpret_cast<uint2*>(&x_s[buf][0][snl+8][sch*4]) = u;
            u.x = packh2(pf[2].x, pf[2].y); u.y = packh2(pf[2].z, pf[2].w);
            *reinterpret_cast<uint2*>(&x_s[buf][1][snl][sch*4]) = u;
            u.x = packh2(pf[3].x, pf[3].y); u.y = packh2(pf[3].z, pf[3].w);
            *reinterpret_cast<uint2*>(&x_s[buf][1][snl+8][sch*4]) = u;
        }
        __syncthreads();

        if (it < 4){
            const int nb = base + 16;
            pf[0] = __ldg(reinterpret_cast<const float4*>(euc + (size_t)(nb+snl)*CH   + sch*4));
            pf[1] = __ldg(reinterpret_cast<const float4*>(euc + (size_t)(nb+snl+8)*CH + sch*4));
            pf[2] = __ldg(reinterpret_cast<const float4*>(geo + (size_t)(nb+snl)*CH   + sch*4));
            pf[3] = __ldg(reinterpret_cast<const float4*>(geo + (size_t)(nb+snl+8)*CH + sch*4));
        }

        // A fragments via ldmatrix.x4 (M16 x K64)
        unsigned af[4][4];
        {
            const int arow = lane & 15;
            const int acol = (lane >> 4) * 8;
            #pragma unroll
            for (int t = 0; t < 4; t++){
                unsigned addr = (unsigned)__cvta_generic_to_shared(
                    &x_s[buf][src][arow][16*t + acol]);
                asm volatile(
                    "ldmatrix.sync.aligned.m8n8.x4.shared.b16 {%0,%1,%2,%3}, [%4];"
                    : "=r"(af[t][0]), "=r"(af[t][1]), "=r"(af[t][2]), "=r"(af[t][3])
                    : "r"(addr));
            }
        }

        float cf[8][4];
        #pragma unroll
        for (int j = 0; j < 8; j++)
            #pragma unroll
            for (int c = 0; c < 4; c++) cf[j][c] = 0.f;

        #pragma unroll
        for (int t = 0; t < 4; t++)
            #pragma unroll
            for (int j = 0; j < 8; j++){
                asm volatile(
                    "mma.sync.aligned.m16n8k16.row.col.f32.f16.f16.f32 "
                    "{%0,%1,%2,%3}, {%4,%5,%6,%7}, {%8,%9}, {%0,%1,%2,%3};"
                    : "+f"(cf[j][0]), "+f"(cf[j][1]), "+f"(cf[j][2]), "+f"(cf[j][3])
                    : "r"(af[t][0]), "r"(af[t][1]), "r"(af[t][2]), "r"(af[t][3]),
                      "r"(bf[t][j][0]), "r"(bf[t][j][1]));
            }

        // epilogue: rows r0 and r0+8
        const int r0 = base + (lane >> 2);
        if (m == 3){
            #pragma unroll
            for (int j = 0; j < 8; j++){
                float2 lo = make_float2(cf[j][0] + bias[j].x, cf[j][1] + bias[j].y);
                float2 hi = make_float2(cf[j][2] + bias[j].x, cf[j][3] + bias[j].y);
                *reinterpret_cast<float2*>(g_skip + (size_t)r0*CH + 8*j + bk2) = lo;
                *reinterpret_cast<float2*>(g_skip + (size_t)(r0+8)*CH + 8*j + bk2) = hi;
            }
        } else {
            __half* O = (m==0) ? g_qh : (m==1) ? g_kh : g_vh;
            #pragma unroll
            for (int j = 0; j < 8; j++){
                unsigned lo = packh2(cf[j][0] + bias[j].x, cf[j][1] + bias[j].y);
                unsigned hi = packh2(cf[j][2] + bias[j].x, cf[j][3] + bias[j].y);
                *reinterpret_cast<unsigned*>(O + (size_t)r0*CH + 8*j + bk2) = lo;
                *reinterpret_cast<unsigned*>(O + (size_t)(r0+8)*CH + 8*j + bk2) = hi;
            }
        }
    }
}

// ---------------------------------------------------------------------------
// fused edge pass, 8 lanes/edge, fp16 q/k/v + ONE red.global.add.noftz.
// v4.f16x2 per lane (8 halves, 16B, single L2 atomic op).
// ---------------------------------------------------------------------------
__global__ void k_edge(const void* __restrict__ ei_raw){
    const int gt  = blockIdx.x*blockDim.x + threadIdx.x;
    const int e   = gt >> 3;
    const int sub = threadIdx.x & 7;

    int src, dst;
    if (g_idx64){
        const long long* ei = (const long long*)ei_raw;
        src = (int)__ldg(ei + e);
        dst = (int)__ldg(ei + NE + e);
    } else {
        const int* ei = (const int*)ei_raw;
        src = __ldg(ei + e);
        dst = __ldg(ei + NE + e);
    }
    src = min(max(src, 0), NN-1);
    dst = min(max(dst, 0), NN-1);

    const uint4* qp = reinterpret_cast<const uint4*>(g_qh) + (size_t)dst*8 + sub;
    const uint4* kp = reinterpret_cast<const uint4*>(g_kh) + (size_t)src*8 + sub;
    const uint4* vp = reinterpret_cast<const uint4*>(g_vh) + (size_t)src*8 + sub;

    uint4 qr = *qp;                    // 8 halves (8 channels)
    uint4 kr = *kp;
    uint4 vr = *vp;

    float d = 0.f;
    #pragma unroll
    for (int j = 0; j < 4; j++){
        float2 qf = __half22float2(reinterpret_cast<const __half2*>(&qr)[j]);
        float2 kf = __half22float2(reinterpret_cast<const __half2*>(&kr)[j]);
        d += qf.x*kf.x + qf.y*kf.y;
    }
    d += __shfl_xor_sync(0xffffffffu, d, 4);
    d += __shfl_xor_sync(0xffffffffu, d, 2);
    d += __shfl_xor_sync(0xffffffffu, d, 1);
    const float ex = __expf(d * 0.125f);   // 1/sqrt(64)

    if (sub == 0) atomicAdd(g_den + dst, ex);

    unsigned p0 = packmul_h2(ex, __half22float2(reinterpret_cast<const __half2*>(&vr)[0]));
    unsigned p1 = packmul_h2(ex, __half22float2(reinterpret_cast<const __half2*>(&vr)[1]));
    unsigned p2 = packmul_h2(ex, __half22float2(reinterpret_cast<const __half2*>(&vr)[2]));
    unsigned p3 = packmul_h2(ex, __half22float2(reinterpret_cast<const __half2*>(&vr)[3]));
    __half* ap = g_agg + (size_t)dst*CH + sub*8;
    asm volatile("red.global.add.noftz.v4.f16x2 [%0], {%1, %2, %3, %4};"
        :: "l"(ap), "r"(p0), "r"(p1), "r"(p2), "r"(p3) : "memory");
}

// ---------------------------------------------------------------------------
// fused finalize (persistent, FGRID co-resident CTAs + spin barrier):
// phase 1: out_pre = agg/(den+1e-16) + skip ; accumulate sum/sumsq
// barrier: g_bar spin (reset each call by k_init)
// phase 2: same thread re-reads ITS OWN out elements, layernorm + relu.
// ---------------------------------------------------------------------------
__global__ void __launch_bounds__(256) k_final(
    float* __restrict__ out,
    const float* __restrict__ lnw, const float* __restrict__ lnb)
{
    float lsum = 0.f, lsq = 0.f;
    const uint4*  agg8  = reinterpret_cast<const uint4*>(g_agg);
    const float4* skip4 = reinterpret_cast<const float4*>(g_skip);
    float4* out4 = reinterpret_cast<float4*>(out);
    const int stride = FGRID*256;

    for (int i = blockIdx.x*blockDim.x + threadIdx.x; i < NN*8; i += stride){
        uint4 a8 = agg8[i];
        float4 s0 = skip4[2*i], s1 = skip4[2*i+1];
        const float inv = 1.f / (g_den[i>>3] + 1e-16f);
        float2 a0 = __half22float2(reinterpret_cast<const __half2*>(&a8)[0]);
        float2 a1 = __half22float2(reinterpret_cast<const __half2*>(&a8)[1]);
        float2 a2 = __half22float2(reinterpret_cast<const __half2*>(&a8)[2]);
        float2 a3 = __half22float2(reinterpret_cast<const __half2*>(&a8)[3]);
        float4 v0, v1;
        v0.x = a0.x*inv + s0.x;  v0.y = a0.y*inv + s0.y;
        v0.z = a1.x*inv + s0.z;  v0.w = a1.y*inv + s0.w;
        v1.x = a2.x*inv + s1.x;  v1.y = a2.y*inv + s1.y;
        v1.z = a3.x*inv + s1.z;  v1.w = a3.y*inv + s1.w;
        out4[2*i]   = v0;
        out4[2*i+1] = v1;
        lsum += v0.x + v0.y + v0.z + v0.w + v1.x + v1.y + v1.z + v1.w;
        lsq  += v0.x*v0.x + v0.y*v0.y + v0.z*v0.z + v0.w*v0.w
              + v1.x*v1.x + v1.y*v1.y + v1.z*v1.z + v1.w*v1.w;
    }
    #pragma unroll
    for (int off=16; off>0; off>>=1){
        lsum += __shfl_xor_sync(0xffffffffu, lsum, off);
        lsq  += __shfl_xor_sync(0xffffffffu, lsq,  off);
    }
    __shared__ float s1m[8], s2m[8];
    const int wid = threadIdx.x >> 5;
    if ((threadIdx.x & 31) == 0){ s1m[wid] = lsum; s2m[wid] = lsq; }
    __syncthreads();
    if (threadIdx.x == 0){
        float ts = 0.f, tq = 0.f;
        #pragma unroll
        for (int i=0;i<8;i++){ ts += s1m[i]; tq += s2m[i]; }
        atomicAdd(&g_red[0], (double)ts);
        atomicAdd(&g_red[1], (double)tq);
        __threadfence();
        atomicAdd(&g_bar, 1u);
        while (*reinterpret_cast<volatile unsigned*>(&g_bar) < (unsigned)FGRID) {}
    }
    __syncthreads();

    const double invM = 1.0 / (double)(NN*CH);
    const double m0 = *reinterpret_cast<volatile double*>(&g_red[0]);
    const double m1 = *reinterpret_cast<volatile double*>(&g_red[1]);
    const float mean = (float)(m0*invM);
    const float var  = (float)(m1*invM) - mean*mean;
    const float rstd = 1.f / (sqrtf(fmaxf(var, 0.f)) + 1e-5f);

    for (int i = blockIdx.x*blockDim.x + threadIdx.x; i < NN*8; i += stride){
        #pragma unroll
        for (int h = 0; h < 2; h++){
            const int idx = 2*i + h;
            const int cb = (idx & 15) * 4;
            const float4 wv = *reinterpret_cast<const float4*>(lnw + cb);
            const float4 bv = *reinterpret_cast<const float4*>(lnb + cb);
            float4 x = out4[idx];
            float4 y;
            y.x = fmaxf((x.x - mean)*rstd*wv.x + bv.x, 0.f);
            y.y = fmaxf((x.y - mean)*rstd*wv.y + bv.y, 0.f);
            y.z = fmaxf((x.z - mean)*rstd*wv.z + bv.z, 0.f);
            y.w = fmaxf((x.w - mean)*rstd*wv.w + bv.w, 0.f);
            out4[idx] = y;
        }
    }
}

// ---------------------------------------------------------------------------
extern "C" void kernel_launch(void* const* d_in, const int* in_sizes, int n_in,
                              void* d_out, int out_size){
    const float* geo = (const float*)d_in[0];
    const float* euc = (const float*)d_in[1];
    const float* Wq  = (const float*)d_in[2];
    const float* bq  = (const float*)d_in[3];
    const float* Wk  = (const float*)d_in[4];
    const float* bk  = (const float*)d_in[5];
    const float* Wv  = (const float*)d_in[6];
    const float* bv  = (const float*)d_in[7];
    const float* Ws  = (const float*)d_in[8];
    const float* bs  = (const float*)d_in[9];
    const float* lnw = (const float*)d_in[10];
    const float* lnb = (const float*)d_in[11];

    const void* ei = d_in[12];
    for (int i = 0; i < n_in; i++)
        if (in_sizes[i] == 2*NE){ ei = d_in[i]; break; }

    float* out = (float*)d_out;

    k_init  <<<NN*8/256, 256>>>((const unsigned int*)ei);
    k_qkvs  <<<1250, 128>>>(geo, euc, Wq, Wk, Wv, Ws, bq, bk, bv, bs);
    k_edge  <<<NE*8/256, 256>>>(ei);
    k_final <<<FGRID, 256>>>(out, lnw, lnb);
}

// round 15
// speedup vs baseline: 2.3937x; 1.0366x over previous
#include <cuda_runtime.h>
#include <cuda_fp16.h>

#define NN 100000
#define NE 1600000
#define CH 64
#define FGRID 148              // persistent final kernel grid (co-resident)
#define FTHR  1024

typedef unsigned long long ull;

// Scratch (device globals — no allocation allowed)
__device__ __align__(16) __half g_qh[NN*CH];   // fp16 q
__device__ __align__(16) __half g_kh[NN*CH];   // fp16 k
__device__ __align__(16) __half g_vh[NN*CH];   // fp16 v
__device__ __align__(16) __half g_agg[NN*CH];  // fp16 accumulator
__device__ __align__(16) float g_skip[NN*CH];
__device__ float g_den[NN];
__device__ double g_red[2];
__device__ unsigned g_bar;
__device__ int g_idx64;

__device__ __forceinline__ unsigned packh2(float a, float b){
    __half2 h = __floats2half2_rn(a, b);
    return *reinterpret_cast<unsigned*>(&h);
}
__device__ __forceinline__ unsigned packmul_h2(float s, float2 v){
    return packh2(s*v.x, s*v.y);
}

// ---------------------------------------------------------------------------
// init: zero den/red/bar + detect edge-index dtype (block 0, warp 0).
// (agg is zeroed inside k_qkvs — each block covers its own node range.)
// ---------------------------------------------------------------------------
__global__ void k_init(const unsigned int* __restrict__ ei32){
    int i = blockIdx.x*blockDim.x + threadIdx.x;
    if (i < NN/4)
        reinterpret_cast<float4*>(g_den)[i] = make_float4(0.f,0.f,0.f,0.f);
    if (i == 0){ g_red[0] = 0.0; g_red[1] = 0.0; g_bar = 0u; }
    if (blockIdx.x == 0 && threadIdx.x < 32){
        unsigned int hi = ei32[2*threadIdx.x + 1];
        unsigned int b = __ballot_sync(0xffffffffu, hi != 0u);
        if (threadIdx.x == 0) g_idx64 = (b == 0u);
    }
}

// ---------------------------------------------------------------------------
// qkvs: tensor-core GEMM (mma.sync.m16n8k16), software-pipelined,
// 128-thread CTAs (4 warps = 4 matrices, 16-node tiles) -> 2 CTAs/SM.
// Also zeroes g_agg for its node range (1 uint4/thread/tile).
// ---------------------------------------------------------------------------
__global__ void __launch_bounds__(128, 2) k_qkvs(
    const float* __restrict__ geo, const float* __restrict__ euc,
    const float* __restrict__ Wq, const float* __restrict__ Wk,
    const float* __restrict__ Wv, const float* __restrict__ Wsk,
    const float* __restrict__ bq, const float* __restrict__ bk,
    const float* __restrict__ bv, const float* __restrict__ bsk)
{
    __shared__ __half x_s[2][2][16][72];  // [buf][src][node][ch]

    const int tid  = threadIdx.x;
    const int wid  = tid >> 5;
    const int lane = tid & 31;
    const int m    = wid;               // 0=q 1=k 2=v 3=skip
    const int src  = (m == 1 || m == 2) ? 1 : 0;   // k,v <- geo; q,skip <- euc

    const float* W  = (m==0)?Wq:(m==1)?Wk:(m==2)?Wv:Wsk;
    const float* Bv = (m==0)?bq:(m==1)?bk:(m==2)?bv:bsk;

    const int bn  = lane >> 2;          // n-in-8 for B/C frags
    const int bk2 = (lane & 3) * 2;     // k/col pair base

    const int snl = tid >> 4;           // node 0..7 (+8 for second chunk)
    const int sch = tid & 15;           // ch-quad 0..15

    // B fragments: [k-tile t][n-tile j][2]
    unsigned bf[4][8][2];
    #pragma unroll
    for (int t = 0; t < 4; t++)
        #pragma unroll
        for (int j = 0; j < 8; j++){
            const float* wr = W + (8*j + bn)*CH + 16*t + bk2;
            float2 w0 = *reinterpret_cast<const float2*>(wr);
            float2 w1 = *reinterpret_cast<const float2*>(wr + 8);
            bf[t][j][0] = packh2(w0.x, w0.y);
            bf[t][j][1] = packh2(w1.x, w1.y);
        }
    float2 bias[8];
    #pragma unroll
    for (int j = 0; j < 8; j++){
        bias[j].x = __ldg(Bv + 8*j + bk2);
        bias[j].y = __ldg(Bv + 8*j + bk2 + 1);
    }

    // prefetch tile 0
    float4 pf[4];
    {
        const int base0 = blockIdx.x*5*16;
        pf[0] = __ldg(reinterpret_cast<const float4*>(euc + (size_t)(base0+snl)*CH   + sch*4));
        pf[1] = __ldg(reinterpret_cast<const float4*>(euc + (size_t)(base0+snl+8)*CH + sch*4));
        pf[2] = __ldg(reinterpret_cast<const float4*>(geo + (size_t)(base0+snl)*CH   + sch*4));
        pf[3] = __ldg(reinterpret_cast<const float4*>(geo + (size_t)(base0+snl+8)*CH + sch*4));
    }

    #pragma unroll 1
    for (int it = 0; it < 5; it++){
        const int base = (blockIdx.x*5 + it) * 16;
        const int buf  = it & 1;

        // zero agg slice for this tile (16 nodes * 8 uint4 = 128 = blockDim)
        reinterpret_cast<uint4*>(g_agg)[(size_t)base*8 + tid] =
            make_uint4(0u,0u,0u,0u);

        {
            uint2 u;
            u.x = packh2(pf[0].x, pf[0].y); u.y = packh2(pf[0].z, pf[0].w);
            *reinterpret_cast<uint2*>(&x_s[buf][0][snl][sch*4]) = u;
            u.x = packh2(pf[1].x, pf[1].y); u.y = packh2(pf[1].z, pf[1].w);
            *reinterpret_cast<uint2*>(&x_s[buf][0][snl+8][sch*4]) = u;
            u.x = packh2(pf[2].x, pf[2].y); u.y = packh2(pf[2].z, pf[2].w);
            *reinterpret_cast<uint2*>(&x_s[buf][1][snl][sch*4]) = u;
            u.x = packh2(pf[3].x, pf[3].y); u.y = packh2(pf[3].z, pf[3].w);
            *reinterpret_cast<uint2*>(&x_s[buf][1][snl+8][sch*4]) = u;
        }
        __syncthreads();

        if (it < 4){
            const int nb = base + 16;
            pf[0] = __ldg(reinterpret_cast<const float4*>(euc + (size_t)(nb+snl)*CH   + sch*4));
            pf[1] = __ldg(reinterpret_cast<const float4*>(euc + (size_t)(nb+snl+8)*CH + sch*4));
            pf[2] = __ldg(reinterpret_cast<const float4*>(geo + (size_t)(nb+snl)*CH   + sch*4));
            pf[3] = __ldg(reinterpret_cast<const float4*>(geo + (size_t)(nb+snl+8)*CH + sch*4));
        }

        // A fragments via ldmatrix.x4 (M16 x K64)
        unsigned af[4][4];
        {
            const int arow = lane & 15;
            const int acol = (lane >> 4) * 8;
            #pragma unroll
            for (int t = 0; t < 4; t++){
                unsigned addr = (unsigned)__cvta_generic_to_shared(
                    &x_s[buf][src][arow][16*t + acol]);
                asm volatile(
                    "ldmatrix.sync.aligned.m8n8.x4.shared.b16 {%0,%1,%2,%3}, [%4];"
                    : "=r"(af[t][0]), "=r"(af[t][1]), "=r"(af[t][2]), "=r"(af[t][3])
                    : "r"(addr));
            }
        }

        float cf[8][4];
        #pragma unroll
        for (int j = 0; j < 8; j++)
            #pragma unroll
            for (int c = 0; c < 4; c++) cf[j][c] = 0.f;

        #pragma unroll
        for (int t = 0; t < 4; t++)
            #pragma unroll
            for (int j = 0; j < 8; j++){
                asm volatile(
                    "mma.sync.aligned.m16n8k16.row.col.f32.f16.f16.f32 "
                    "{%0,%1,%2,%3}, {%4,%5,%6,%7}, {%8,%9}, {%0,%1,%2,%3};"
                    : "+f"(cf[j][0]), "+f"(cf[j][1]), "+f"(cf[j][2]), "+f"(cf[j][3])
                    : "r"(af[t][0]), "r"(af[t][1]), "r"(af[t][2]), "r"(af[t][3]),
                      "r"(bf[t][j][0]), "r"(bf[t][j][1]));
            }

        // epilogue: rows r0 and r0+8
        const int r0 = base + (lane >> 2);
        if (m == 3){
            #pragma unroll
            for (int j = 0; j < 8; j++){
                float2 lo = make_float2(cf[j][0] + bias[j].x, cf[j][1] + bias[j].y);
                float2 hi = make_float2(cf[j][2] + bias[j].x, cf[j][3] + bias[j].y);
                *reinterpret_cast<float2*>(g_skip + (size_t)r0*CH + 8*j + bk2) = lo;
                *reinterpret_cast<float2*>(g_skip + (size_t)(r0+8)*CH + 8*j + bk2) = hi;
            }
        } else {
            __half* O = (m==0) ? g_qh : (m==1) ? g_kh : g_vh;
            #pragma unroll
            for (int j = 0; j < 8; j++){
                unsigned lo = packh2(cf[j][0] + bias[j].x, cf[j][1] + bias[j].y);
                unsigned hi = packh2(cf[j][2] + bias[j].x, cf[j][3] + bias[j].y);
                *reinterpret_cast<unsigned*>(O + (size_t)r0*CH + 8*j + bk2) = lo;
                *reinterpret_cast<unsigned*>(O + (size_t)(r0+8)*CH + 8*j + bk2) = hi;
            }
        }
    }
}

// ---------------------------------------------------------------------------
// fused edge pass, 8 lanes/edge, fp16 q/k/v + ONE red.global.add.noftz.
// v4.f16x2 per lane (8 halves, 16B, single L2 atomic op).
// ---------------------------------------------------------------------------
__global__ void k_edge(const void* __restrict__ ei_raw){
    const int gt  = blockIdx.x*blockDim.x + threadIdx.x;
    const int e   = gt >> 3;
    const int sub = threadIdx.x & 7;

    int src, dst;
    if (g_idx64){
        const long long* ei = (const long long*)ei_raw;
        src = (int)__ldg(ei + e);
        dst = (int)__ldg(ei + NE + e);
    } else {
        const int* ei = (const int*)ei_raw;
        src = __ldg(ei + e);
        dst = __ldg(ei + NE + e);
    }
    src = min(max(src, 0), NN-1);
    dst = min(max(dst, 0), NN-1);

    const uint4* qp = reinterpret_cast<const uint4*>(g_qh) + (size_t)dst*8 + sub;
    const uint4* kp = reinterpret_cast<const uint4*>(g_kh) + (size_t)src*8 + sub;
    const uint4* vp = reinterpret_cast<const uint4*>(g_vh) + (size_t)src*8 + sub;

    uint4 qr = *qp;                    // 8 halves (8 channels)
    uint4 kr = *kp;
    uint4 vr = *vp;

    float d = 0.f;
    #pragma unroll
    for (int j = 0; j < 4; j++){
        float2 qf = __half22float2(reinterpret_cast<const __half2*>(&qr)[j]);
        float2 kf = __half22float2(reinterpret_cast<const __half2*>(&kr)[j]);
        d += qf.x*kf.x + qf.y*kf.y;
    }
    d += __shfl_xor_sync(0xffffffffu, d, 4);
    d += __shfl_xor_sync(0xffffffffu, d, 2);
    d += __shfl_xor_sync(0xffffffffu, d, 1);
    const float ex = __expf(d * 0.125f);   // 1/sqrt(64)

    if (sub == 0) atomicAdd(g_den + dst, ex);

    unsigned p0 = packmul_h2(ex, __half22float2(reinterpret_cast<const __half2*>(&vr)[0]));
    unsigned p1 = packmul_h2(ex, __half22float2(reinterpret_cast<const __half2*>(&vr)[1]));
    unsigned p2 = packmul_h2(ex, __half22float2(reinterpret_cast<const __half2*>(&vr)[2]));
    unsigned p3 = packmul_h2(ex, __half22float2(reinterpret_cast<const __half2*>(&vr)[3]));
    __half* ap = g_agg + (size_t)dst*CH + sub*8;
    asm volatile("red.global.add.noftz.v4.f16x2 [%0], {%1, %2, %3, %4};"
        :: "l"(ap), "r"(p0), "r"(p1), "r"(p2), "r"(p3) : "memory");
}

// ---------------------------------------------------------------------------
// fused finalize (persistent, FGRID x 1024 co-resident + spin barrier):
// phase 1: sums of val = agg/(den+1e-16)+skip  (NO store)
// phase 2: recompute val (L2-warm), layernorm + relu, single out store.
// ---------------------------------------------------------------------------
__global__ void __launch_bounds__(FTHR) k_final(
    float* __restrict__ out,
    const float* __restrict__ lnw, const float* __restrict__ lnb)
{
    const uint4*  agg8  = reinterpret_cast<const uint4*>(g_agg);
    const float4* skip4 = reinterpret_cast<const float4*>(g_skip);
    float4* out4 = reinterpret_cast<float4*>(out);
    const int stride = FGRID*FTHR;

    float lsum = 0.f, lsq = 0.f;
    for (int i = blockIdx.x*blockDim.x + threadIdx.x; i < NN*8; i += stride){
        uint4 a8 = agg8[i];
        float4 s0 = skip4[2*i], s1 = skip4[2*i+1];
        const float inv = 1.f / (g_den[i>>3] + 1e-16f);
        float2 a0 = __half22float2(reinterpret_cast<const __half2*>(&a8)[0]);
        float2 a1 = __half22float2(reinterpret_cast<const __half2*>(&a8)[1]);
        float2 a2 = __half22float2(reinterpret_cast<const __half2*>(&a8)[2]);
        float2 a3 = __half22float2(reinterpret_cast<const __half2*>(&a8)[3]);
        float v0 = a0.x*inv + s0.x, v1 = a0.y*inv + s0.y;
        float v2 = a1.x*inv + s0.z, v3 = a1.y*inv + s0.w;
        float v4 = a2.x*inv + s1.x, v5 = a2.y*inv + s1.y;
        float v6 = a3.x*inv + s1.z, v7 = a3.y*inv + s1.w;
        lsum += v0+v1+v2+v3+v4+v5+v6+v7;
        lsq  += v0*v0+v1*v1+v2*v2+v3*v3+v4*v4+v5*v5+v6*v6+v7*v7;
    }
    #pragma unroll
    for (int off=16; off>0; off>>=1){
        lsum += __shfl_xor_sync(0xffffffffu, lsum, off);
        lsq  += __shfl_xor_sync(0xffffffffu, lsq,  off);
    }
    __shared__ float s1m[32], s2m[32];
    const int wid = threadIdx.x >> 5;
    if ((threadIdx.x & 31) == 0){ s1m[wid] = lsum; s2m[wid] = lsq; }
    __syncthreads();
    if (threadIdx.x == 0){
        float ts = 0.f, tq = 0.f;
        #pragma unroll
        for (int i=0;i<32;i++){ ts += s1m[i]; tq += s2m[i]; }
        atomicAdd(&g_red[0], (double)ts);
        atomicAdd(&g_red[1], (double)tq);
        __threadfence();
        atomicAdd(&g_bar, 1u);
        while (*reinterpret_cast<volatile unsigned*>(&g_bar) < (unsigned)FGRID) {}
    }
    __syncthreads();

    const double invM = 1.0 / (double)(NN*CH);
    const double m0 = *reinterpret_cast<volatile double*>(&g_red[0]);
    const double m1 = *reinterpret_cast<volatile double*>(&g_red[1]);
    const float mean = (float)(m0*invM);
    const float var  = (float)(m1*invM) - mean*mean;
    const float rstd = 1.f / (sqrtf(fmaxf(var, 0.f)) + 1e-5f);

    for (int i = blockIdx.x*blockDim.x + threadIdx.x; i < NN*8; i += stride){
        uint4 a8 = agg8[i];
        float4 s0 = skip4[2*i], s1 = skip4[2*i+1];
        const float inv = 1.f / (g_den[i>>3] + 1e-16f);
        float2 a0 = __half22float2(reinterpret_cast<const __half2*>(&a8)[0]);
        float2 a1 = __half22float2(reinterpret_cast<const __half2*>(&a8)[1]);
        float2 a2 = __half22float2(reinterpret_cast<const __half2*>(&a8)[2]);
        float2 a3 = __half22float2(reinterpret_cast<const __half2*>(&a8)[3]);
        const int cb = (i & 7) * 8;     // channel base (node-major, 8ch/i)
        const float4 w0 = *reinterpret_cast<const float4*>(lnw + cb);
        const float4 w1 = *reinterpret_cast<const float4*>(lnw + cb + 4);
        const float4 b0 = *reinterpret_cast<const float4*>(lnb + cb);
        const float4 b1 = *reinterpret_cast<const float4*>(lnb + cb + 4);
        float4 y0, y1;
        y0.x = fmaxf((a0.x*inv + s0.x - mean)*rstd*w0.x + b0.x, 0.f);
        y0.y = fmaxf((a0.y*inv + s0.y - mean)*rstd*w0.y + b0.y, 0.f);
        y0.z = fmaxf((a1.x*inv + s0.z - mean)*rstd*w0.z + b0.z, 0.f);
        y0.w = fmaxf((a1.y*inv + s0.w - mean)*rstd*w0.w + b0.w, 0.f);
        y1.x = fmaxf((a2.x*inv + s1.x - mean)*rstd*w1.x + b1.x, 0.f);
        y1.y = fmaxf((a2.y*inv + s1.y - mean)*rstd*w1.y + b1.y, 0.f);
        y1.z = fmaxf((a3.x*inv + s1.z - mean)*rstd*w1.z + b1.z, 0.f);
        y1.w = fmaxf((a3.y*inv + s1.w - mean)*rstd*w1.w + b1.w, 0.f);
        out4[2*i]   = y0;
        out4[2*i+1] = y1;
    }
}

// ---------------------------------------------------------------------------
extern "C" void kernel_launch(void* const* d_in, const int* in_sizes, int n_in,
                              void* d_out, int out_size){
    const float* geo = (const float*)d_in[0];
    const float* euc = (const float*)d_in[1];
    const float* Wq  = (const float*)d_in[2];
    const float* bq  = (const float*)d_in[3];
    const float* Wk  = (const float*)d_in[4];
    const float* bk  = (const float*)d_in[5];
    const float* Wv  = (const float*)d_in[6];
    const float* bv  = (const float*)d_in[7];
    const float* Ws  = (const float*)d_in[8];
    const float* bs  = (const float*)d_in[9];
    const float* lnw = (const float*)d_in[10];
    const float* lnb = (const float*)d_in[11];

    const void* ei = d_in[12];
    for (int i = 0; i < n_in; i++)
        if (in_sizes[i] == 2*NE){ ei = d_in[i]; break; }

    float* out = (float*)d_out;

    k_init  <<<(NN/4 + 255)/256, 256>>>((const unsigned int*)ei);
    k_qkvs  <<<1250, 128>>>(geo, euc, Wq, Wk, Wv, Ws, bq, bk, bv, bs);
    k_edge  <<<NE*8/256, 256>>>(ei);
    k_final <<<FGRID, FTHR>>>(out, lnw, lnb);
}

// round 16
// speedup vs baseline: 2.4573x; 1.0266x over previous
#include <cuda_runtime.h>
#include <cuda_fp16.h>

#define NN 100000
#define NE 1600000
#define CH 64
#define FGRID 296              // persistent final kernel grid (2 CTAs/SM)
#define FTHR  512

typedef unsigned long long ull;

// Scratch (device globals — no allocation allowed)
__device__ __align__(16) __half g_qh[NN*CH];   // fp16 q
__device__ __align__(16) __half g_kh[NN*CH];   // fp16 k
__device__ __align__(16) __half g_vh[NN*CH];   // fp16 v
__device__ __align__(16) __half g_agg[NN*CH];  // fp16 accumulator
__device__ __align__(16) float g_skip[NN*CH];
__device__ float g_den[NN];
__device__ double g_red[2];
__device__ unsigned g_bar;
__device__ int g_idx64;

__device__ __forceinline__ unsigned packh2(float a, float b){
    __half2 h = __floats2half2_rn(a, b);
    return *reinterpret_cast<unsigned*>(&h);
}
__device__ __forceinline__ unsigned packmul_h2(float s, float2 v){
    return packh2(s*v.x, s*v.y);
}

// ---------------------------------------------------------------------------
// qkvs: tensor-core GEMM (mma.sync.m16n8k16), software-pipelined,
// 128-thread CTAs (4 warps = 4 matrices, 16-node tiles) -> 2 CTAs/SM.
// Also: zeroes g_agg for its node range, zeroes its g_den slice, block 0
// resets g_red/g_bar and detects the edge-index dtype (replaces k_init).
// ---------------------------------------------------------------------------
__global__ void __launch_bounds__(128, 2) k_qkvs(
    const float* __restrict__ geo, const float* __restrict__ euc,
    const float* __restrict__ Wq, const float* __restrict__ Wk,
    const float* __restrict__ Wv, const float* __restrict__ Wsk,
    const float* __restrict__ bq, const float* __restrict__ bk,
    const float* __restrict__ bv, const float* __restrict__ bsk,
    const unsigned int* __restrict__ ei32)
{
    __shared__ __half x_s[2][2][16][72];  // [buf][src][node][ch]

    const int tid  = threadIdx.x;
    const int wid  = tid >> 5;
    const int lane = tid & 31;
    const int m    = wid;               // 0=q 1=k 2=v 3=skip
    const int src  = (m == 1 || m == 2) ? 1 : 0;   // k,v <- geo; q,skip <- euc

    // init duties (replaces k_init)
    if (tid < 20)
        reinterpret_cast<float4*>(g_den)[blockIdx.x*20 + tid] =
            make_float4(0.f,0.f,0.f,0.f);
    if (blockIdx.x == 0){
        if (tid == 0){ g_red[0] = 0.0; g_red[1] = 0.0; g_bar = 0u; }
        if (wid == 1){
            unsigned int hi = ei32[2*lane + 1];
            unsigned int b = __ballot_sync(0xffffffffu, hi != 0u);
            if (lane == 0) g_idx64 = (b == 0u);
        }
    }

    const float* W  = (m==0)?Wq:(m==1)?Wk:(m==2)?Wv:Wsk;
    const float* Bv = (m==0)?bq:(m==1)?bk:(m==2)?bv:bsk;

    const int bn  = lane >> 2;          // n-in-8 for B/C frags
    const int bk2 = (lane & 3) * 2;     // k/col pair base

    const int snl = tid >> 4;           // node 0..7 (+8 for second chunk)
    const int sch = tid & 15;           // ch-quad 0..15

    // B fragments: [k-tile t][n-tile j][2]
    unsigned bf[4][8][2];
    #pragma unroll
    for (int t = 0; t < 4; t++)
        #pragma unroll
        for (int j = 0; j < 8; j++){
            const float* wr = W + (8*j + bn)*CH + 16*t + bk2;
            float2 w0 = *reinterpret_cast<const float2*>(wr);
            float2 w1 = *reinterpret_cast<const float2*>(wr + 8);
            bf[t][j][0] = packh2(w0.x, w0.y);
            bf[t][j][1] = packh2(w1.x, w1.y);
        }
    float2 bias[8];
    #pragma unroll
    for (int j = 0; j < 8; j++){
        bias[j].x = __ldg(Bv + 8*j + bk2);
        bias[j].y = __ldg(Bv + 8*j + bk2 + 1);
    }

    // prefetch tile 0
    float4 pf[4];
    {
        const int base0 = blockIdx.x*5*16;
        pf[0] = __ldg(reinterpret_cast<const float4*>(euc + (size_t)(base0+snl)*CH   + sch*4));
        pf[1] = __ldg(reinterpret_cast<const float4*>(euc + (size_t)(base0+snl+8)*CH + sch*4));
        pf[2] = __ldg(reinterpret_cast<const float4*>(geo + (size_t)(base0+snl)*CH   + sch*4));
        pf[3] = __ldg(reinterpret_cast<const float4*>(geo + (size_t)(base0+snl+8)*CH + sch*4));
    }

    #pragma unroll 1
    for (int it = 0; it < 5; it++){
        const int base = (blockIdx.x*5 + it) * 16;
        const int buf  = it & 1;

        // zero agg slice for this tile (16 nodes * 8 uint4 = 128 = blockDim)
        reinterpret_cast<uint4*>(g_agg)[(size_t)base*8 + tid] =
            make_uint4(0u,0u,0u,0u);

        {
            uint2 u;
            u.x = packh2(pf[0].x, pf[0].y); u.y = packh2(pf[0].z, pf[0].w);
            *reinterpret_cast<uint2*>(&x_s[buf][0][snl][sch*4]) = u;
            u.x = packh2(pf[1].x, pf[1].y); u.y = packh2(pf[1].z, pf[1].w);
            *reinterpret_cast<uint2*>(&x_s[buf][0][snl+8][sch*4]) = u;
            u.x = packh2(pf[2].x, pf[2].y); u.y = packh2(pf[2].z, pf[2].w);
            *reinterpret_cast<uint2*>(&x_s[buf][1][snl][sch*4]) = u;
            u.x = packh2(pf[3].x, pf[3].y); u.y = packh2(pf[3].z, pf[3].w);
            *reinterpret_cast<uint2*>(&x_s[buf][1][snl+8][sch*4]) = u;
        }
        __syncthreads();

        if (it < 4){
            const int nb = base + 16;
            pf[0] = __ldg(reinterpret_cast<const float4*>(euc + (size_t)(nb+snl)*CH   + sch*4));
            pf[1] = __ldg(reinterpret_cast<const float4*>(euc + (size_t)(nb+snl+8)*CH + sch*4));
            pf[2] = __ldg(reinterpret_cast<const float4*>(geo + (size_t)(nb+snl)*CH   + sch*4));
            pf[3] = __ldg(reinterpret_cast<const float4*>(geo + (size_t)(nb+snl+8)*CH + sch*4));
        }

        // A fragments via ldmatrix.x4 (M16 x K64)
        unsigned af[4][4];
        {
            const int arow = lane & 15;
            const int acol = (lane >> 4) * 8;
            #pragma unroll
            for (int t = 0; t < 4; t++){
                unsigned addr = (unsigned)__cvta_generic_to_shared(
                    &x_s[buf][src][arow][16*t + acol]);
                asm volatile(
                    "ldmatrix.sync.aligned.m8n8.x4.shared.b16 {%0,%1,%2,%3}, [%4];"
                    : "=r"(af[t][0]), "=r"(af[t][1]), "=r"(af[t][2]), "=r"(af[t][3])
                    : "r"(addr));
            }
        }

        float cf[8][4];
        #pragma unroll
        for (int j = 0; j < 8; j++)
            #pragma unroll
            for (int c = 0; c < 4; c++) cf[j][c] = 0.f;

        #pragma unroll
        for (int t = 0; t < 4; t++)
            #pragma unroll
            for (int j = 0; j < 8; j++){
                asm volatile(
                    "mma.sync.aligned.m16n8k16.row.col.f32.f16.f16.f32 "
                    "{%0,%1,%2,%3}, {%4,%5,%6,%7}, {%8,%9}, {%0,%1,%2,%3};"
                    : "+f"(cf[j][0]), "+f"(cf[j][1]), "+f"(cf[j][2]), "+f"(cf[j][3])
                    : "r"(af[t][0]), "r"(af[t][1]), "r"(af[t][2]), "r"(af[t][3]),
                      "r"(bf[t][j][0]), "r"(bf[t][j][1]));
            }

        // epilogue: rows r0 and r0+8
        const int r0 = base + (lane >> 2);
        if (m == 3){
            #pragma unroll
            for (int j = 0; j < 8; j++){
                float2 lo = make_float2(cf[j][0] + bias[j].x, cf[j][1] + bias[j].y);
                float2 hi = make_float2(cf[j][2] + bias[j].x, cf[j][3] + bias[j].y);
                *reinterpret_cast<float2*>(g_skip + (size_t)r0*CH + 8*j + bk2) = lo;
                *reinterpret_cast<float2*>(g_skip + (size_t)(r0+8)*CH + 8*j + bk2) = hi;
            }
        } else {
            __half* O = (m==0) ? g_qh : (m==1) ? g_kh : g_vh;
            #pragma unroll
            for (int j = 0; j < 8; j++){
                unsigned lo = packh2(cf[j][0] + bias[j].x, cf[j][1] + bias[j].y);
                unsigned hi = packh2(cf[j][2] + bias[j].x, cf[j][3] + bias[j].y);
                *reinterpret_cast<unsigned*>(O + (size_t)r0*CH + 8*j + bk2) = lo;
                *reinterpret_cast<unsigned*>(O + (size_t)(r0+8)*CH + 8*j + bk2) = hi;
            }
        }
    }
}

// ---------------------------------------------------------------------------
// fused edge pass, 8 lanes/edge, fp16 q/k/v + ONE red.global.add.noftz.
// v4.f16x2 per lane (8 halves, 16B, single L2 atomic op).
// ---------------------------------------------------------------------------
__global__ void k_edge(const void* __restrict__ ei_raw){
    const int gt  = blockIdx.x*blockDim.x + threadIdx.x;
    const int e   = gt >> 3;
    const int sub = threadIdx.x & 7;

    int src, dst;
    if (g_idx64){
        const long long* ei = (const long long*)ei_raw;
        src = (int)__ldg(ei + e);
        dst = (int)__ldg(ei + NE + e);
    } else {
        const int* ei = (const int*)ei_raw;
        src = __ldg(ei + e);
        dst = __ldg(ei + NE + e);
    }
    src = min(max(src, 0), NN-1);
    dst = min(max(dst, 0), NN-1);

    const uint4* qp = reinterpret_cast<const uint4*>(g_qh) + (size_t)dst*8 + sub;
    const uint4* kp = reinterpret_cast<const uint4*>(g_kh) + (size_t)src*8 + sub;
    const uint4* vp = reinterpret_cast<const uint4*>(g_vh) + (size_t)src*8 + sub;

    uint4 qr = *qp;                    // 8 halves (8 channels)
    uint4 kr = *kp;
    uint4 vr = *vp;

    float d = 0.f;
    #pragma unroll
    for (int j = 0; j < 4; j++){
        float2 qf = __half22float2(reinterpret_cast<const __half2*>(&qr)[j]);
        float2 kf = __half22float2(reinterpret_cast<const __half2*>(&kr)[j]);
        d += qf.x*kf.x + qf.y*kf.y;
    }
    d += __shfl_xor_sync(0xffffffffu, d, 4);
    d += __shfl_xor_sync(0xffffffffu, d, 2);
    d += __shfl_xor_sync(0xffffffffu, d, 1);
    const float ex = __expf(d * 0.125f);   // 1/sqrt(64)

    if (sub == 0) atomicAdd(g_den + dst, ex);

    unsigned p0 = packmul_h2(ex, __half22float2(reinterpret_cast<const __half2*>(&vr)[0]));
    unsigned p1 = packmul_h2(ex, __half22float2(reinterpret_cast<const __half2*>(&vr)[1]));
    unsigned p2 = packmul_h2(ex, __half22float2(reinterpret_cast<const __half2*>(&vr)[2]));
    unsigned p3 = packmul_h2(ex, __half22float2(reinterpret_cast<const __half2*>(&vr)[3]));
    __half* ap = g_agg + (size_t)dst*CH + sub*8;
    asm volatile("red.global.add.noftz.v4.f16x2 [%0], {%1, %2, %3, %4};"
        :: "l"(ap), "r"(p0), "r"(p1), "r"(p2), "r"(p3) : "memory");
}

// ---------------------------------------------------------------------------
// fused finalize (persistent, FGRID x FTHR = 2 CTAs/SM + spin barrier):
// phase 1: sums of val = agg/(den+1e-16)+skip  (NO store)
// phase 2: recompute val (L2-warm), layernorm + relu, single out store.
// ---------------------------------------------------------------------------
__global__ void __launch_bounds__(FTHR, 2) k_final(
    float* __restrict__ out,
    const float* __restrict__ lnw, const float* __restrict__ lnb)
{
    const uint4*  agg8  = reinterpret_cast<const uint4*>(g_agg);
    const float4* skip4 = reinterpret_cast<const float4*>(g_skip);
    float4* out4 = reinterpret_cast<float4*>(out);
    const int stride = FGRID*FTHR;

    float lsum = 0.f, lsq = 0.f;
    #pragma unroll 2
    for (int i = blockIdx.x*blockDim.x + threadIdx.x; i < NN*8; i += stride){
        uint4 a8 = agg8[i];
        float4 s0 = skip4[2*i], s1 = skip4[2*i+1];
        const float inv = 1.f / (g_den[i>>3] + 1e-16f);
        float2 a0 = __half22float2(reinterpret_cast<const __half2*>(&a8)[0]);
        float2 a1 = __half22float2(reinterpret_cast<const __half2*>(&a8)[1]);
        float2 a2 = __half22float2(reinterpret_cast<const __half2*>(&a8)[2]);
        float2 a3 = __half22float2(reinterpret_cast<const __half2*>(&a8)[3]);
        float v0 = a0.x*inv + s0.x, v1 = a0.y*inv + s0.y;
        float v2 = a1.x*inv + s0.z, v3 = a1.y*inv + s0.w;
        float v4 = a2.x*inv + s1.x, v5 = a2.y*inv + s1.y;
        float v6 = a3.x*inv + s1.z, v7 = a3.y*inv + s1.w;
        lsum += v0+v1+v2+v3+v4+v5+v6+v7;
        lsq  += v0*v0+v1*v1+v2*v2+v3*v3+v4*v4+v5*v5+v6*v6+v7*v7;
    }
    #pragma unroll
    for (int off=16; off>0; off>>=1){
        lsum += __shfl_xor_sync(0xffffffffu, lsum, off);
        lsq  += __shfl_xor_sync(0xffffffffu, lsq,  off);
    }
    __shared__ float s1m[16], s2m[16];
    const int wid = threadIdx.x >> 5;
    if ((threadIdx.x & 31) == 0){ s1m[wid] = lsum; s2m[wid] = lsq; }
    __syncthreads();
    if (threadIdx.x == 0){
        float ts = 0.f, tq = 0.f;
        #pragma unroll
        for (int i=0;i<16;i++){ ts += s1m[i]; tq += s2m[i]; }
        atomicAdd(&g_red[0], (double)ts);
        atomicAdd(&g_red[1], (double)tq);
        __threadfence();
        atomicAdd(&g_bar, 1u);
        while (*reinterpret_cast<volatile unsigned*>(&g_bar) < (unsigned)FGRID) {}
    }
    __syncthreads();

    const double invM = 1.0 / (double)(NN*CH);
    const double m0 = *reinterpret_cast<volatile double*>(&g_red[0]);
    const double m1 = *reinterpret_cast<volatile double*>(&g_red[1]);
    const float mean = (float)(m0*invM);
    const float var  = (float)(m1*invM) - mean*mean;
    const float rstd = 1.f / (sqrtf(fmaxf(var, 0.f)) + 1e-5f);

    #pragma unroll 2
    for (int i = blockIdx.x*blockDim.x + threadIdx.x; i < NN*8; i += stride){
        uint4 a8 = agg8[i];
        float4 s0 = skip4[2*i], s1 = skip4[2*i+1];
        const float inv = 1.f / (g_den[i>>3] + 1e-16f);
        float2 a0 = __half22float2(reinterpret_cast<const __half2*>(&a8)[0]);
        float2 a1 = __half22float2(reinterpret_cast<const __half2*>(&a8)[1]);
        float2 a2 = __half22float2(reinterpret_cast<const __half2*>(&a8)[2]);
        float2 a3 = __half22float2(reinterpret_cast<const __half2*>(&a8)[3]);
        const int cb = (i & 7) * 8;     // channel base (node-major, 8ch/i)
        const float4 w0 = *reinterpret_cast<const float4*>(lnw + cb);
        const float4 w1 = *reinterpret_cast<const float4*>(lnw + cb + 4);
        const float4 b0 = *reinterpret_cast<const float4*>(lnb + cb);
        const float4 b1 = *reinterpret_cast<const float4*>(lnb + cb + 4);
        float4 y0, y1;
        y0.x = fmaxf((a0.x*inv + s0.x - mean)*rstd*w0.x + b0.x, 0.f);
        y0.y = fmaxf((a0.y*inv + s0.y - mean)*rstd*w0.y + b0.y, 0.f);
        y0.z = fmaxf((a1.x*inv + s0.z - mean)*rstd*w0.z + b0.z, 0.f);
        y0.w = fmaxf((a1.y*inv + s0.w - mean)*rstd*w0.w + b0.w, 0.f);
        y1.x = fmaxf((a2.x*inv + s1.x - mean)*rstd*w1.x + b1.x, 0.f);
        y1.y = fmaxf((a2.y*inv + s1.y - mean)*rstd*w1.y + b1.y, 0.f);
        y1.z = fmaxf((a3.x*inv + s1.z - mean)*rstd*w1.z + b1.z, 0.f);
        y1.w = fmaxf((a3.y*inv + s1.w - mean)*rstd*w1.w + b1.w, 0.f);
        out4[2*i]   = y0;
        out4[2*i+1] = y1;
    }
}

// ---------------------------------------------------------------------------
extern "C" void kernel_launch(void* const* d_in, const int* in_sizes, int n_in,
                              void* d_out, int out_size){
    const float* geo = (const float*)d_in[0];
    const float* euc = (const float*)d_in[1];
    const float* Wq  = (const float*)d_in[2];
    const float* bq  = (const float*)d_in[3];
    const float* Wk  = (const float*)d_in[4];
    const float* bk  = (const float*)d_in[5];
    const float* Wv  = (const float*)d_in[6];
    const float* bv  = (const float*)d_in[7];
    const float* Ws  = (const float*)d_in[8];
    const float* bs  = (const float*)d_in[9];
    const float* lnw = (const float*)d_in[10];
    const float* lnb = (const float*)d_in[11];

    const void* ei = d_in[12];
    for (int i = 0; i < n_in; i++)
        if (in_sizes[i] == 2*NE){ ei = d_in[i]; break; }

    float* out = (float*)d_out;

    k_qkvs  <<<1250, 128>>>(geo, euc, Wq, Wk, Wv, Ws, bq, bk, bv, bs,
                            (const unsigned int*)ei);
    k_edge  <<<NE*8/256, 256>>>(ei);
    k_final <<<FGRID, FTHR>>>(out, lnw, lnb);
}

// round 17
// speedup vs baseline: 2.5024x; 1.0184x over previous
#include <cuda_runtime.h>
#include <cuda_fp16.h>

#define NN 100000
#define NE 1600000
#define CH 64
#define FGRID 296              // persistent final kernel grid (2 CTAs/SM)
#define FTHR  512

typedef unsigned long long ull;

// Scratch (device globals — no allocation allowed)
__device__ __align__(16) __half g_qh[NN*CH];   // fp16 q
__device__ __align__(16) __half g_kh[NN*CH];   // fp16 k
__device__ __align__(16) __half g_vh[NN*CH];   // fp16 v
__device__ __align__(16) __half g_agg[NN*CH];  // fp16 accumulator
__device__ __align__(16) float g_skip[NN*CH];
__device__ float g_den[NN];
__device__ double g_red[2];
__device__ unsigned g_bar;
__device__ int g_idx64;

__device__ __forceinline__ unsigned packh2(float a, float b){
    __half2 h = __floats2half2_rn(a, b);
    return *reinterpret_cast<unsigned*>(&h);
}
__device__ __forceinline__ unsigned packmul_h2(float s, float2 v){
    return packh2(s*v.x, s*v.y);
}

// ---------------------------------------------------------------------------
// qkvs v12: tensor-core GEMM (mma.sync.m16n8k16), software-pipelined,
// 256-thread CTAs, 8 warps = (matrix m = w&3, n-half = w>>2): each warp
// M16 x N32 x K64 -> regs ~halved -> 2 CTAs/SM = 16 warps/SM.
// Also zeroes g_agg slice + g_den slice; block 0 resets g_red/g_bar and
// detects the edge-index dtype.
// ---------------------------------------------------------------------------
__global__ void __launch_bounds__(256, 2) k_qkvs(
    const float* __restrict__ geo, const float* __restrict__ euc,
    const float* __restrict__ Wq, const float* __restrict__ Wk,
    const float* __restrict__ Wv, const float* __restrict__ Wsk,
    const float* __restrict__ bq, const float* __restrict__ bk,
    const float* __restrict__ bv, const float* __restrict__ bsk,
    const unsigned int* __restrict__ ei32)
{
    __shared__ __half x_s[2][2][16][72];  // [buf][src][node][ch]

    const int tid  = threadIdx.x;
    const int wid  = tid >> 5;
    const int lane = tid & 31;
    const int m    = wid & 3;           // 0=q 1=k 2=v 3=skip
    const int nh   = wid >> 2;          // n-half: channels nh*32 .. nh*32+31
    const int src  = (m == 1 || m == 2) ? 1 : 0;   // k,v <- geo; q,skip <- euc

    // init duties
    if (tid < 20)
        reinterpret_cast<float4*>(g_den)[blockIdx.x*20 + tid] =
            make_float4(0.f,0.f,0.f,0.f);
    if (blockIdx.x == 0){
        if (tid == 0){ g_red[0] = 0.0; g_red[1] = 0.0; g_bar = 0u; }
        if (wid == 1){
            unsigned int hi = ei32[2*lane + 1];
            unsigned int b = __ballot_sync(0xffffffffu, hi != 0u);
            if (lane == 0) g_idx64 = (b == 0u);
        }
    }

    const float* W  = (m==0)?Wq:(m==1)?Wk:(m==2)?Wv:Wsk;
    const float* Bv = (m==0)?bq:(m==1)?bk:(m==2)?bv:bsk;

    const int bn  = lane >> 2;          // n-in-8 for B/C frags
    const int bk2 = (lane & 3) * 2;     // k/col pair base

    const int snl = tid >> 4;           // node 0..15
    const int sch = tid & 15;           // ch-quad 0..15

    // B fragments: [k-tile t][n-tile j][2], j covers N32 = 4 x 8
    unsigned bf[4][4][2];
    #pragma unroll
    for (int t = 0; t < 4; t++)
        #pragma unroll
        for (int j = 0; j < 4; j++){
            const float* wr = W + (nh*32 + 8*j + bn)*CH + 16*t + bk2;
            float2 w0 = *reinterpret_cast<const float2*>(wr);
            float2 w1 = *reinterpret_cast<const float2*>(wr + 8);
            bf[t][j][0] = packh2(w0.x, w0.y);
            bf[t][j][1] = packh2(w1.x, w1.y);
        }
    float2 bias[4];
    #pragma unroll
    for (int j = 0; j < 4; j++){
        bias[j].x = __ldg(Bv + nh*32 + 8*j + bk2);
        bias[j].y = __ldg(Bv + nh*32 + 8*j + bk2 + 1);
    }

    // prefetch tile 0 (one euc + one geo float4 per thread)
    float4 pfe, pfg;
    {
        const int base0 = blockIdx.x*5*16;
        pfe = __ldg(reinterpret_cast<const float4*>(euc + (size_t)(base0+snl)*CH + sch*4));
        pfg = __ldg(reinterpret_cast<const float4*>(geo + (size_t)(base0+snl)*CH + sch*4));
    }

    #pragma unroll 1
    for (int it = 0; it < 5; it++){
        const int base = (blockIdx.x*5 + it) * 16;
        const int buf  = it & 1;

        // zero agg slice (16 nodes * 8 uint4 = 128)
        if (tid < 128)
            reinterpret_cast<uint4*>(g_agg)[(size_t)base*8 + tid] =
                make_uint4(0u,0u,0u,0u);

        {
            uint2 u;
            u.x = packh2(pfe.x, pfe.y); u.y = packh2(pfe.z, pfe.w);
            *reinterpret_cast<uint2*>(&x_s[buf][0][snl][sch*4]) = u;
            u.x = packh2(pfg.x, pfg.y); u.y = packh2(pfg.z, pfg.w);
            *reinterpret_cast<uint2*>(&x_s[buf][1][snl][sch*4]) = u;
        }
        __syncthreads();

        if (it < 4){
            const int nb = base + 16;
            pfe = __ldg(reinterpret_cast<const float4*>(euc + (size_t)(nb+snl)*CH + sch*4));
            pfg = __ldg(reinterpret_cast<const float4*>(geo + (size_t)(nb+snl)*CH + sch*4));
        }

        // A fragments via ldmatrix.x4 (M16 x K64) — same for both n-halves
        unsigned af[4][4];
        {
            const int arow = lane & 15;
            const int acol = (lane >> 4) * 8;
            #pragma unroll
            for (int t = 0; t < 4; t++){
                unsigned addr = (unsigned)__cvta_generic_to_shared(
                    &x_s[buf][src][arow][16*t + acol]);
                asm volatile(
                    "ldmatrix.sync.aligned.m8n8.x4.shared.b16 {%0,%1,%2,%3}, [%4];"
                    : "=r"(af[t][0]), "=r"(af[t][1]), "=r"(af[t][2]), "=r"(af[t][3])
                    : "r"(addr));
            }
        }

        float cf[4][4];
        #pragma unroll
        for (int j = 0; j < 4; j++)
            #pragma unroll
            for (int c = 0; c < 4; c++) cf[j][c] = 0.f;

        #pragma unroll
        for (int t = 0; t < 4; t++)
            #pragma unroll
            for (int j = 0; j < 4; j++){
                asm volatile(
                    "mma.sync.aligned.m16n8k16.row.col.f32.f16.f16.f32 "
                    "{%0,%1,%2,%3}, {%4,%5,%6,%7}, {%8,%9}, {%0,%1,%2,%3};"
                    : "+f"(cf[j][0]), "+f"(cf[j][1]), "+f"(cf[j][2]), "+f"(cf[j][3])
                    : "r"(af[t][0]), "r"(af[t][1]), "r"(af[t][2]), "r"(af[t][3]),
                      "r"(bf[t][j][0]), "r"(bf[t][j][1]));
            }

        // epilogue: rows r0 and r0+8, columns nh*32 + 8j + bk2
        const int r0 = base + (lane >> 2);
        const int cb0 = nh*32 + bk2;
        if (m == 3){
            #pragma unroll
            for (int j = 0; j < 4; j++){
                float2 lo = make_float2(cf[j][0] + bias[j].x, cf[j][1] + bias[j].y);
                float2 hi = make_float2(cf[j][2] + bias[j].x, cf[j][3] + bias[j].y);
                *reinterpret_cast<float2*>(g_skip + (size_t)r0*CH + cb0 + 8*j) = lo;
                *reinterpret_cast<float2*>(g_skip + (size_t)(r0+8)*CH + cb0 + 8*j) = hi;
            }
        } else {
            __half* O = (m==0) ? g_qh : (m==1) ? g_kh : g_vh;
            #pragma unroll
            for (int j = 0; j < 4; j++){
                unsigned lo = packh2(cf[j][0] + bias[j].x, cf[j][1] + bias[j].y);
                unsigned hi = packh2(cf[j][2] + bias[j].x, cf[j][3] + bias[j].y);
                *reinterpret_cast<unsigned*>(O + (size_t)r0*CH + cb0 + 8*j) = lo;
                *reinterpret_cast<unsigned*>(O + (size_t)(r0+8)*CH + cb0 + 8*j) = hi;
            }
        }
    }
}

// ---------------------------------------------------------------------------
// fused edge pass, 8 lanes/edge, fp16 q/k/v + ONE red.global.add.noftz.
// v4.f16x2 per lane (8 halves, 16B, single L2 atomic op).
// ---------------------------------------------------------------------------
__global__ void k_edge(const void* __restrict__ ei_raw){
    const int gt  = blockIdx.x*blockDim.x + threadIdx.x;
    const int e   = gt >> 3;
    const int sub = threadIdx.x & 7;

    int src, dst;
    if (g_idx64){
        const long long* ei = (const long long*)ei_raw;
        src = (int)__ldg(ei + e);
        dst = (int)__ldg(ei + NE + e);
    } else {
        const int* ei = (const int*)ei_raw;
        src = __ldg(ei + e);
        dst = __ldg(ei + NE + e);
    }
    src = min(max(src, 0), NN-1);
    dst = min(max(dst, 0), NN-1);

    const uint4* qp = reinterpret_cast<const uint4*>(g_qh) + (size_t)dst*8 + sub;
    const uint4* kp = reinterpret_cast<const uint4*>(g_kh) + (size_t)src*8 + sub;
    const uint4* vp = reinterpret_cast<const uint4*>(g_vh) + (size_t)src*8 + sub;

    uint4 qr = *qp;                    // 8 halves (8 channels)
    uint4 kr = *kp;
    uint4 vr = *vp;

    float d = 0.f;
    #pragma unroll
    for (int j = 0; j < 4; j++){
        float2 qf = __half22float2(reinterpret_cast<const __half2*>(&qr)[j]);
        float2 kf = __half22float2(reinterpret_cast<const __half2*>(&kr)[j]);
        d += qf.x*kf.x + qf.y*kf.y;
    }
    d += __shfl_xor_sync(0xffffffffu, d, 4);
    d += __shfl_xor_sync(0xffffffffu, d, 2);
    d += __shfl_xor_sync(0xffffffffu, d, 1);
    const float ex = __expf(d * 0.125f);   // 1/sqrt(64)

    if (sub == 0) atomicAdd(g_den + dst, ex);

    unsigned p0 = packmul_h2(ex, __half22float2(reinterpret_cast<const __half2*>(&vr)[0]));
    unsigned p1 = packmul_h2(ex, __half22float2(reinterpret_cast<const __half2*>(&vr)[1]));
    unsigned p2 = packmul_h2(ex, __half22float2(reinterpret_cast<const __half2*>(&vr)[2]));
    unsigned p3 = packmul_h2(ex, __half22float2(reinterpret_cast<const __half2*>(&vr)[3]));
    __half* ap = g_agg + (size_t)dst*CH + sub*8;
    asm volatile("red.global.add.noftz.v4.f16x2 [%0], {%1, %2, %3, %4};"
        :: "l"(ap), "r"(p0), "r"(p1), "r"(p2), "r"(p3) : "memory");
}

// ---------------------------------------------------------------------------
// fused finalize (persistent, FGRID x FTHR = 2 CTAs/SM + spin barrier):
// phase 1: sums of val = agg/(den+1e-16)+skip  (NO store)
// phase 2: recompute val (L2-warm), layernorm + relu, single out store.
// ---------------------------------------------------------------------------
__global__ void __launch_bounds__(FTHR, 2) k_final(
    float* __restrict__ out,
    const float* __restrict__ lnw, const float* __restrict__ lnb)
{
    const uint4*  agg8  = reinterpret_cast<const uint4*>(g_agg);
    const float4* skip4 = reinterpret_cast<const float4*>(g_skip);
    float4* out4 = reinterpret_cast<float4*>(out);
    const int stride = FGRID*FTHR;

    float lsum = 0.f, lsq = 0.f;
    #pragma unroll 2
    for (int i = blockIdx.x*blockDim.x + threadIdx.x; i < NN*8; i += stride){
        uint4 a8 = agg8[i];
        float4 s0 = skip4[2*i], s1 = skip4[2*i+1];
        const float inv = 1.f / (g_den[i>>3] + 1e-16f);
        float2 a0 = __half22float2(reinterpret_cast<const __half2*>(&a8)[0]);
        float2 a1 = __half22float2(reinterpret_cast<const __half2*>(&a8)[1]);
        float2 a2 = __half22float2(reinterpret_cast<const __half2*>(&a8)[2]);
        float2 a3 = __half22float2(reinterpret_cast<const __half2*>(&a8)[3]);
        float v0 = a0.x*inv + s0.x, v1 = a0.y*inv + s0.y;
        float v2 = a1.x*inv + s0.z, v3 = a1.y*inv + s0.w;
        float v4 = a2.x*inv + s1.x, v5 = a2.y*inv + s1.y;
        float v6 = a3.x*inv + s1.z, v7 = a3.y*inv + s1.w;
        lsum += v0+v1+v2+v3+v4+v5+v6+v7;
        lsq  += v0*v0+v1*v1+v2*v2+v3*v3+v4*v4+v5*v5+v6*v6+v7*v7;
    }
    #pragma unroll
    for (int off=16; off>0; off>>=1){
        lsum += __shfl_xor_sync(0xffffffffu, lsum, off);
        lsq  += __shfl_xor_sync(0xffffffffu, lsq,  off);
    }
    __shared__ float s1m[16], s2m[16];
    const int wid = threadIdx.x >> 5;
    if ((threadIdx.x & 31) == 0){ s1m[wid] = lsum; s2m[wid] = lsq; }
    __syncthreads();
    if (threadIdx.x == 0){
        float ts = 0.f, tq = 0.f;
        #pragma unroll
        for (int i=0;i<16;i++){ ts += s1m[i]; tq += s2m[i]; }
        atomicAdd(&g_red[0], (double)ts);
        atomicAdd(&g_red[1], (double)tq);
        __threadfence();
        atomicAdd(&g_bar, 1u);
        while (*reinterpret_cast<volatile unsigned*>(&g_bar) < (unsigned)FGRID) {}
    }
    __syncthreads();

    const double invM = 1.0 / (double)(NN*CH);
    const double m0 = *reinterpret_cast<volatile double*>(&g_red[0]);
    const double m1 = *reinterpret_cast<volatile double*>(&g_red[1]);
    const float mean = (float)(m0*invM);
    const float var  = (float)(m1*invM) - mean*mean;
    const float rstd = 1.f / (sqrtf(fmaxf(var, 0.f)) + 1e-5f);

    #pragma unroll 2
    for (int i = blockIdx.x*blockDim.x + threadIdx.x; i < NN*8; i += stride){
        uint4 a8 = agg8[i];
        float4 s0 = skip4[2*i], s1 = skip4[2*i+1];
        const float inv = 1.f / (g_den[i>>3] + 1e-16f);
        float2 a0 = __half22float2(reinterpret_cast<const __half2*>(&a8)[0]);
        float2 a1 = __half22float2(reinterpret_cast<const __half2*>(&a8)[1]);
        float2 a2 = __half22float2(reinterpret_cast<const __half2*>(&a8)[2]);
        float2 a3 = __half22float2(reinterpret_cast<const __half2*>(&a8)[3]);
        const int cb = (i & 7) * 8;     // channel base (node-major, 8ch/i)
        const float4 w0 = *reinterpret_cast<const float4*>(lnw + cb);
        const float4 w1 = *reinterpret_cast<const float4*>(lnw + cb + 4);
        const float4 b0 = *reinterpret_cast<const float4*>(lnb + cb);
        const float4 b1 = *reinterpret_cast<const float4*>(lnb + cb + 4);
        float4 y0, y1;
        y0.x = fmaxf((a0.x*inv + s0.x - mean)*rstd*w0.x + b0.x, 0.f);
        y0.y = fmaxf((a0.y*inv + s0.y - mean)*rstd*w0.y + b0.y, 0.f);
        y0.z = fmaxf((a1.x*inv + s0.z - mean)*rstd*w0.z + b0.z, 0.f);
        y0.w = fmaxf((a1.y*inv + s0.w - mean)*rstd*w0.w + b0.w, 0.f);
        y1.x = fmaxf((a2.x*inv + s1.x - mean)*rstd*w1.x + b1.x, 0.f);
        y1.y = fmaxf((a2.y*inv + s1.y - mean)*rstd*w1.y + b1.y, 0.f);
        y1.z = fmaxf((a3.x*inv + s1.z - mean)*rstd*w1.z + b1.z, 0.f);
        y1.w = fmaxf((a3.y*inv + s1.w - mean)*rstd*w1.w + b1.w, 0.f);
        out4[2*i]   = y0;
        out4[2*i+1] = y1;
    }
}

// ---------------------------------------------------------------------------
extern "C" void kernel_launch(void* const* d_in, const int* in_sizes, int n_in,
                              void* d_out, int out_size){
    const float* geo = (const float*)d_in[0];
    const float* euc = (const float*)d_in[1];
    const float* Wq  = (const float*)d_in[2];
    const float* bq  = (const float*)d_in[3];
    const float* Wk  = (const float*)d_in[4];
    const float* bk  = (const float*)d_in[5];
    const float* Wv  = (const float*)d_in[6];
    const float* bv  = (const float*)d_in[7];
    const float* Ws  = (const float*)d_in[8];
    const float* bs  = (const float*)d_in[9];
    const float* lnw = (const float*)d_in[10];
    const float* lnb = (const float*)d_in[11];

    const void* ei = d_in[12];
    for (int i = 0; i < n_in; i++)
        if (in_sizes[i] == 2*NE){ ei = d_in[i]; break; }

    float* out = (float*)d_out;

    k_qkvs  <<<1250, 256>>>(geo, euc, Wq, Wk, Wv, Ws, bq, bk, bv, bs,
                            (const unsigned int*)ei);
    k_edge  <<<NE*8/256, 256>>>(ei);
    k_final <<<FGRID, FTHR>>>(out, lnw, lnb);
}